// round 1
// baseline (speedup 1.0000x reference)
#include <cuda_runtime.h>
#include <math.h>

// Problem constants
#define BB   2
#define TT   2048
#define CC   1024
#define NH   16
#define LAT  512
#define DHR  64
#define MR   (BB*TT)        // 4096 rows

// ---------------------------------------------------------------------------
// Scratch (static device globals; cudaMalloc is forbidden)
// ---------------------------------------------------------------------------
__device__ float g_h  [MR * 1024];   // x@w1+b1          [4096,1024]
__device__ float g_kr [MR * 64];     // rope(h@wkr+bkr)  [4096,64]
__device__ float g_qr [MR * 1024];   // rope(h@wqr+bqr)  [4096,1024]
__device__ float g_kv [MR * 2048];   // cKV@wkv+bkv  (k cols 0..1023, v cols 1024..2047)
__device__ float g_q  [MR * 1024];   // cq@wq+bq
__device__ float g_att[MR * 1024];   // attention output [B,T,NH*DK]

// ---------------------------------------------------------------------------
// Generic fp32 GEMM + bias: C[M,N] = A[M,K] @ B[K,N] + bias[N]
// A has row stride lda (allows column-sliced views of g_h). ldb = ldc = N.
// Requires: M % BM == 0, N % BN == 0, K % BK == 0 (true for all call sites).
// ---------------------------------------------------------------------------
template<int BM, int BN, int BK, int TM, int TN>
__global__ __launch_bounds__((BM/TM)*(BN/TN))
void gemm_bias_kernel(int M, int N, int K,
                      const float* __restrict__ A, int lda,
                      const float* __restrict__ B,
                      const float* __restrict__ bias,
                      float* __restrict__ C)
{
    constexpr int THREADS = (BM/TM)*(BN/TN);
    constexpr int A_ITERS = (BM*BK)/(4*THREADS);
    constexpr int B_ITERS = (BN*BK)/(4*THREADS);
    static_assert(A_ITERS*4*THREADS == BM*BK, "A tile not evenly loadable");
    static_assert(B_ITERS*4*THREADS == BN*BK, "B tile not evenly loadable");

    __shared__ float As[BK][BM];
    __shared__ float Bs[BK][BN];

    const int tid  = threadIdx.x;
    const int bRow = blockIdx.y * BM;
    const int bCol = blockIdx.x * BN;
    const int tCol = (tid % (BN/TN)) * TN;
    const int tRow = (tid / (BN/TN)) * TM;

    float acc[TM][TN];
#pragma unroll
    for (int i = 0; i < TM; i++)
#pragma unroll
        for (int j = 0; j < TN; j++) acc[i][j] = 0.f;

    for (int k0 = 0; k0 < K; k0 += BK) {
#pragma unroll
        for (int it = 0; it < A_ITERS; it++) {
            int idx = tid + it*THREADS;
            int r = idx / (BK/4);
            int c = (idx % (BK/4)) * 4;
            float4 a4 = *reinterpret_cast<const float4*>(
                A + (size_t)(bRow + r)*lda + k0 + c);
            As[c+0][r] = a4.x; As[c+1][r] = a4.y;
            As[c+2][r] = a4.z; As[c+3][r] = a4.w;
        }
#pragma unroll
        for (int it = 0; it < B_ITERS; it++) {
            int idx = tid + it*THREADS;
            int r = idx / (BN/4);
            int c = (idx % (BN/4)) * 4;
            *reinterpret_cast<float4*>(&Bs[r][c]) =
                *reinterpret_cast<const float4*>(B + (size_t)(k0 + r)*N + bCol + c);
        }
        __syncthreads();

#pragma unroll
        for (int kk = 0; kk < BK; kk++) {
            float ra[TM], rb[TN];
#pragma unroll
            for (int i = 0; i < TM; i++) ra[i] = As[kk][tRow + i];
#pragma unroll
            for (int j = 0; j < TN; j++) rb[j] = Bs[kk][tCol + j];
#pragma unroll
            for (int i = 0; i < TM; i++)
#pragma unroll
                for (int j = 0; j < TN; j++)
                    acc[i][j] += ra[i] * rb[j];
        }
        __syncthreads();
    }

#pragma unroll
    for (int i = 0; i < TM; i++) {
#pragma unroll
        for (int j = 0; j < TN; j += 4) {
            int col = bCol + tCol + j;
            float4 o;
            o.x = acc[i][j+0] + bias[col+0];
            o.y = acc[i][j+1] + bias[col+1];
            o.z = acc[i][j+2] + bias[col+2];
            o.w = acc[i][j+3] + bias[col+3];
            *reinterpret_cast<float4*>(C + (size_t)(bRow + tRow + i)*N + col) = o;
        }
    }
}

// ---------------------------------------------------------------------------
// RoPE in-place over rows of x[MR, D], rotary dim d == D (matches reference:
// kR uses D=d=64, qR uses D=d=1024 applied BEFORE the per-head reshape).
// freq = t+1, theta_i = 10000^(-2i/d), pair (even, odd) rotation.
// ---------------------------------------------------------------------------
__global__ void rope_kernel(float* __restrict__ x, int D)
{
    const int pairs = D / 2;
    int idx = blockIdx.x * blockDim.x + threadIdx.x;
    if (idx >= MR * pairs) return;
    int row = idx / pairs;
    int i   = idx - row * pairs;
    int t   = row & (TT - 1);

    // mirror reference fp32 math: exp(-2*i/d * ln(10000))
    float theta = expf(-2.0f * (float)i / (float)D * 9.2103403719761836f);
    float ang   = (float)(t + 1) * theta;
    float sn, cs;
    sincosf(ang, &sn, &cs);

    float* p = x + (size_t)row * D + 2*i;
    float e = p[0], o = p[1];
    p[0] = e * cs - o * sn;
    p[1] = o * cs + e * sn;
}

// ---------------------------------------------------------------------------
// Causal flash attention, fp32. dqk = 128 (64 nope + 64 rope), dv = 64.
// One block = 64 query rows of one (batch, head). 256 threads.
// ---------------------------------------------------------------------------
#define AT_PAD 68

struct __align__(16) AttnSmem {
    float Qt[128][AT_PAD];   // Q transposed [d][r], pre-scaled by 1/sqrt(128)
    float Kt[128][AT_PAD];   // K transposed [d][c]
    float Ss[64][AT_PAD];    // scores then probabilities [r][c]
    float Vs[64][AT_PAD];    // V tile [j][c]
    float m[64];
    float l[64];
    float alpha[64];
};

__global__ __launch_bounds__(256, 2)
void attn_kernel()
{
    extern __shared__ char smem_raw[];
    AttnSmem& S = *reinterpret_cast<AttnSmem*>(smem_raw);

    const int tid = threadIdx.x;
    const int qt  = blockIdx.x;     // 0..31
    const int hh  = blockIdx.y;     // 0..15
    const int b   = blockIdx.z;     // 0..1
    const int base = b * TT + qt * 64;
    const float scale = 0.08838834764831845f;   // 128^-0.5

    // load Q tile (transposed, pre-scaled)
    for (int idx = tid; idx < 64*128; idx += 256) {
        int r = idx >> 7, d = idx & 127;
        float v = (d < 64)
            ? g_q [(size_t)(base + r)*1024 + hh*64 + d]
            : g_qr[(size_t)(base + r)*1024 + hh*64 + (d - 64)];
        S.Qt[d][r] = v * scale;
    }
    if (tid < 64) { S.m[tid] = -1e30f; S.l[tid] = 0.f; }

    const int tx = tid & 15, ty = tid >> 4;
    const int c0 = tx * 4,  r0 = ty * 4;

    float o[4][4];
#pragma unroll
    for (int i = 0; i < 4; i++)
#pragma unroll
        for (int j = 0; j < 4; j++) o[i][j] = 0.f;

    for (int kt = 0; kt <= qt; kt++) {
        __syncthreads();   // prior-iter PV reads done (also covers Q-load on iter 0)

        // load K (transposed) and V tiles
        for (int idx = tid; idx < 64*128; idx += 256) {
            int c = idx >> 7, d = idx & 127;
            int krow = b * TT + kt*64 + c;
            S.Kt[d][c] = (d < 64)
                ? g_kv[(size_t)krow*2048 + hh*64 + d]
                : g_kr[(size_t)krow*64   + (d - 64)];
        }
        for (int idx = tid; idx < 64*64; idx += 256) {
            int j = idx >> 6, c = idx & 63;
            S.Vs[j][c] = g_kv[(size_t)(b*TT + kt*64 + j)*2048 + 1024 + hh*64 + c];
        }
        __syncthreads();

        // S = (Q*scale) @ K^T  (4x4 register tile per thread)
        float sa[4][4];
#pragma unroll
        for (int i = 0; i < 4; i++)
#pragma unroll
            for (int j = 0; j < 4; j++) sa[i][j] = 0.f;

#pragma unroll 4
        for (int d = 0; d < 128; d++) {
            float4 qa = *reinterpret_cast<const float4*>(&S.Qt[d][r0]);
            float4 kb = *reinterpret_cast<const float4*>(&S.Kt[d][c0]);
            float qv[4] = {qa.x, qa.y, qa.z, qa.w};
            float kv[4] = {kb.x, kb.y, kb.z, kb.w};
#pragma unroll
            for (int i = 0; i < 4; i++)
#pragma unroll
                for (int j = 0; j < 4; j++)
                    sa[i][j] += qv[i] * kv[j];
        }

        // causal mask + write scores
        const bool diag = (kt == qt);
#pragma unroll
        for (int i = 0; i < 4; i++)
#pragma unroll
            for (int j = 0; j < 4; j++) {
                float v = sa[i][j];
                if (diag && (c0 + j) > (r0 + i)) v = -1e30f;
                S.Ss[r0 + i][c0 + j] = v;
            }
        __syncthreads();

        // online softmax row pass (one thread per row)
        if (tid < 64) {
            int r = tid;
            float mo = S.m[r];
            float mx = mo;
#pragma unroll 8
            for (int j = 0; j < 64; j++) mx = fmaxf(mx, S.Ss[r][j]);
            float al = __expf(mo - mx);
            float sum = 0.f;
#pragma unroll 8
            for (int j = 0; j < 64; j++) {
                float p = __expf(S.Ss[r][j] - mx);
                S.Ss[r][j] = p;
                sum += p;
            }
            S.m[r] = mx;
            S.l[r] = S.l[r] * al + sum;
            S.alpha[r] = al;
        }
        __syncthreads();

        // rescale O, accumulate O += P @ V
#pragma unroll
        for (int i = 0; i < 4; i++) {
            float al = S.alpha[r0 + i];
#pragma unroll
            for (int j = 0; j < 4; j++) o[i][j] *= al;
        }
#pragma unroll 4
        for (int j = 0; j < 64; j++) {
            float4 vv = *reinterpret_cast<const float4*>(&S.Vs[j][c0]);
#pragma unroll
            for (int i = 0; i < 4; i++) {
                float p = S.Ss[r0 + i][j];
                o[i][0] += p * vv.x;
                o[i][1] += p * vv.y;
                o[i][2] += p * vv.z;
                o[i][3] += p * vv.w;
            }
        }
    }

    // finalize: divide by l, write [B,T,NH*DK] rows
#pragma unroll
    for (int i = 0; i < 4; i++) {
        float inv = 1.0f / S.l[r0 + i];
        float4 ov;
        ov.x = o[i][0] * inv;
        ov.y = o[i][1] * inv;
        ov.z = o[i][2] * inv;
        ov.w = o[i][3] * inv;
        *reinterpret_cast<float4*>(
            &g_att[(size_t)(base + r0 + i)*1024 + hh*64 + c0]) = ov;
    }
}

// ---------------------------------------------------------------------------
// Launch
// ---------------------------------------------------------------------------
extern "C" void kernel_launch(void* const* d_in, const int* in_sizes, int n_in,
                              void* d_out, int out_size)
{
    (void)in_sizes; (void)n_in; (void)out_size;
    const float* x   = (const float*)d_in[0];
    const float* w1  = (const float*)d_in[1];
    const float* b1  = (const float*)d_in[2];
    const float* wkr = (const float*)d_in[3];
    const float* bkr = (const float*)d_in[4];
    const float* wqr = (const float*)d_in[5];
    const float* bqr = (const float*)d_in[6];
    const float* wkv = (const float*)d_in[7];
    const float* bkv = (const float*)d_in[8];
    const float* wq  = (const float*)d_in[9];
    const float* bq  = (const float*)d_in[10];
    const float* wo  = (const float*)d_in[11];
    const float* bo  = (const float*)d_in[12];
    float* out = (float*)d_out;

    float *h_, *kr_, *qr_, *kv_, *q_, *att_;
    cudaGetSymbolAddress((void**)&h_,   g_h);
    cudaGetSymbolAddress((void**)&kr_,  g_kr);
    cudaGetSymbolAddress((void**)&qr_,  g_qr);
    cudaGetSymbolAddress((void**)&kv_,  g_kv);
    cudaGetSymbolAddress((void**)&q_,   g_q);
    cudaGetSymbolAddress((void**)&att_, g_att);

    // 1) h = x @ w1 + b1                 [4096,1024] x [1024,1024]
    gemm_bias_kernel<128,128,8,8,8><<<dim3(1024/128, MR/128), 256>>>(
        MR, 1024, 1024, x, 1024, w1, b1, h_);

    // 2) kr = rope(h @ wkr + bkr, 64)    [4096,1024] x [1024,64]
    gemm_bias_kernel<128,64,16,8,4><<<dim3(64/64, MR/128), 256>>>(
        MR, 64, 1024, h_, 1024, wkr, bkr, kr_);
    {
        int n = MR * (64/2);
        rope_kernel<<<(n + 255)/256, 256>>>(kr_, 64);
    }

    // 3) qr = rope(h @ wqr + bqr, 1024)  [4096,1024] x [1024,1024]
    gemm_bias_kernel<128,128,8,8,8><<<dim3(1024/128, MR/128), 256>>>(
        MR, 1024, 1024, h_, 1024, wqr, bqr, qr_);
    {
        int n = MR * (1024/2);
        rope_kernel<<<(n + 255)/256, 256>>>(qr_, 1024);
    }

    // 4) kv = cKV @ wkv + bkv            [4096,512] x [512,2048]  (cKV = h[:, :512])
    gemm_bias_kernel<128,128,8,8,8><<<dim3(2048/128, MR/128), 256>>>(
        MR, 2048, 512, h_, 1024, wkv, bkv, kv_);

    // 5) q = cq @ wq + bq                [4096,512] x [512,1024]  (cq = h[:, 512:])
    gemm_bias_kernel<128,128,8,8,8><<<dim3(1024/128, MR/128), 256>>>(
        MR, 1024, 512, h_ + 512, 1024, wq, bq, q_);

    // 6) causal attention -> g_att
    cudaFuncSetAttribute(attn_kernel,
                         cudaFuncAttributeMaxDynamicSharedMemorySize,
                         (int)sizeof(AttnSmem));
    attn_kernel<<<dim3(TT/64, NH, BB), 256, sizeof(AttnSmem)>>>();

    // 7) out = att @ wo + bo             [4096,1024] x [1024,1024]
    gemm_bias_kernel<128,128,8,8,8><<<dim3(1024/128, MR/128), 256>>>(
        MR, 1024, 1024, att_, 1024, wo, bo, out);
}

// round 2
// speedup vs baseline: 1.4816x; 1.4816x over previous
#include <cuda_runtime.h>
#include <math.h>
#include <stdint.h>

// Problem constants
#define BB   2
#define TT   2048
#define CC   1024
#define NH   16
#define LAT  512
#define DHR  64
#define MR   (BB*TT)        // 4096 rows

// ---------------------------------------------------------------------------
// Scratch (static device globals; cudaMalloc is forbidden)
// ---------------------------------------------------------------------------
__device__ float g_h  [MR * 1024];   // x@w1+b1          [4096,1024]
__device__ float g_kr [MR * 64];     // rope(h@wkr+bkr)  [4096,64]
__device__ float g_qr [MR * 1024];   // rope(h@wqr+bqr)  [4096,1024]
__device__ float g_kv [MR * 2048];   // cKV@wkv+bkv  (k cols 0..1023, v cols 1024..2047)
__device__ float g_q  [MR * 1024];   // cq@wq+bq
__device__ float g_att[MR * 1024];   // attention output [B,T,NH*DK]

// ---------------------------------------------------------------------------
// tf32 helpers
// ---------------------------------------------------------------------------
__device__ __forceinline__ uint32_t f2tf(float f) {
    uint32_t u;
    asm("cvt.rna.tf32.f32 %0, %1;" : "=r"(u) : "f"(f));
    return u;
}

__device__ __forceinline__ void mma8(float* c,
                                     uint32_t a0, uint32_t a1, uint32_t a2, uint32_t a3,
                                     uint32_t b0, uint32_t b1) {
    asm volatile(
        "mma.sync.aligned.m16n8k8.row.col.f32.tf32.tf32.f32 "
        "{%0,%1,%2,%3},{%4,%5,%6,%7},{%8,%9},{%0,%1,%2,%3};"
        : "+f"(c[0]), "+f"(c[1]), "+f"(c[2]), "+f"(c[3])
        : "r"(a0), "r"(a1), "r"(a2), "r"(a3), "r"(b0), "r"(b1));
}

// ---------------------------------------------------------------------------
// tf32 tensor-core GEMM + bias: C[M,N] = A[M,K] @ B[K,N] + bias[N]
// BM x BN x 32 tiles, 8 warps (4x2), warp tile = (BM/4) x (BN/2).
// A smem: [BM][32] with XOR-swizzled float4 groups (conflict-free both ways).
// B smem: [32][BN+8]  (stride % 32 == 8 -> conflict-free frag loads).
// Requires M%BM==0, N%BN==0, K%32==0 (true at all call sites).
// ---------------------------------------------------------------------------
template<int BM, int BN>
__global__ __launch_bounds__(256, 2)
void gemm_tf32(int M, int N, int K,
               const float* __restrict__ A, int lda,
               const float* __restrict__ B,
               const float* __restrict__ bias,
               float* __restrict__ C)
{
    constexpr int WM   = BM / 4;      // warp rows
    constexpr int WN   = BN / 2;      // warp cols
    constexpr int MT   = WM / 16;     // m16 tiles per warp
    constexpr int NT   = WN / 8;      // n8 tiles per warp
    constexpr int BSTR = BN + 8;
    constexpr int NA   = BM / 32;     // float4 A loads per thread
    constexpr int NB   = BN / 32;     // float4 B loads per thread

    __shared__ float As[BM * 32];
    __shared__ float Bs[32 * BSTR];

    const int tid  = threadIdx.x;
    const int lane = tid & 31;
    const int warp = tid >> 5;
    const int g    = lane >> 2;       // groupID
    const int t    = lane & 3;        // threadID_in_group
    const int wm   = warp >> 1;
    const int wn   = warp & 1;
    const int bRow = blockIdx.y * BM;
    const int bCol = blockIdx.x * BN;

    float acc[MT][NT][4];
#pragma unroll
    for (int mt = 0; mt < MT; mt++)
#pragma unroll
        for (int nt = 0; nt < NT; nt++)
#pragma unroll
            for (int i = 0; i < 4; i++) acc[mt][nt][i] = 0.f;

    float4 pa[NA], pb[NB];

    auto loadGlobal = [&](int k0) {
#pragma unroll
        for (int i = 0; i < NA; i++) {
            int idx = tid + i * 256;
            int r = idx >> 3, c4 = idx & 7;
            pa[i] = *reinterpret_cast<const float4*>(
                A + (size_t)(bRow + r) * lda + k0 + c4 * 4);
        }
#pragma unroll
        for (int i = 0; i < NB; i++) {
            int idx = tid + i * 256;
            int r = idx / (BN / 4), c4 = idx % (BN / 4);
            pb[i] = *reinterpret_cast<const float4*>(
                B + (size_t)(k0 + r) * N + bCol + c4 * 4);
        }
    };

    auto storeSmem = [&]() {
#pragma unroll
        for (int i = 0; i < NA; i++) {
            int idx = tid + i * 256;
            int r = idx >> 3, c4 = idx & 7;
            float4 v = pa[i], s;
            s.x = __uint_as_float(f2tf(v.x));
            s.y = __uint_as_float(f2tf(v.y));
            s.z = __uint_as_float(f2tf(v.z));
            s.w = __uint_as_float(f2tf(v.w));
            *reinterpret_cast<float4*>(&As[r * 32 + ((c4 ^ (r & 7)) << 2)]) = s;
        }
#pragma unroll
        for (int i = 0; i < NB; i++) {
            int idx = tid + i * 256;
            int r = idx / (BN / 4), c4 = idx % (BN / 4);
            float4 v = pb[i], s;
            s.x = __uint_as_float(f2tf(v.x));
            s.y = __uint_as_float(f2tf(v.y));
            s.z = __uint_as_float(f2tf(v.z));
            s.w = __uint_as_float(f2tf(v.w));
            *reinterpret_cast<float4*>(&Bs[r * BSTR + c4 * 4]) = s;
        }
    };

    const int iters = K / 32;
    loadGlobal(0);
    storeSmem();
    __syncthreads();

    for (int it = 0; it < iters; it++) {
        if (it + 1 < iters) loadGlobal((it + 1) * 32);

#pragma unroll
        for (int kk = 0; kk < 4; kk++) {
            uint32_t af[MT][4];
#pragma unroll
            for (int mt = 0; mt < MT; mt++) {
                int r0 = wm * WM + mt * 16 + g;      // (r0 & 7) == g
                int r1 = r0 + 8;
                int s0 = (2 * kk) ^ g;
                int s1 = (2 * kk + 1) ^ g;
                af[mt][0] = __float_as_uint(As[r0 * 32 + (s0 << 2) + t]);
                af[mt][1] = __float_as_uint(As[r1 * 32 + (s0 << 2) + t]);
                af[mt][2] = __float_as_uint(As[r0 * 32 + (s1 << 2) + t]);
                af[mt][3] = __float_as_uint(As[r1 * 32 + (s1 << 2) + t]);
            }
#pragma unroll
            for (int nt = 0; nt < NT; nt++) {
                int nb = wn * WN + nt * 8 + g;
                uint32_t b0 = __float_as_uint(Bs[(kk * 8 + t)     * BSTR + nb]);
                uint32_t b1 = __float_as_uint(Bs[(kk * 8 + t + 4) * BSTR + nb]);
#pragma unroll
                for (int mt = 0; mt < MT; mt++)
                    mma8(acc[mt][nt], af[mt][0], af[mt][1], af[mt][2], af[mt][3], b0, b1);
            }
        }
        __syncthreads();
        if (it + 1 < iters) storeSmem();
        __syncthreads();
    }

    // epilogue: add bias, write fp32
#pragma unroll
    for (int mt = 0; mt < MT; mt++) {
        int r0 = bRow + wm * WM + mt * 16 + g;
#pragma unroll
        for (int nt = 0; nt < NT; nt++) {
            int col = bCol + wn * WN + nt * 8 + 2 * t;
            float bx = bias[col], by = bias[col + 1];
            float2 v0 = {acc[mt][nt][0] + bx, acc[mt][nt][1] + by};
            float2 v1 = {acc[mt][nt][2] + bx, acc[mt][nt][3] + by};
            *reinterpret_cast<float2*>(C + (size_t)r0 * N + col)       = v0;
            *reinterpret_cast<float2*>(C + (size_t)(r0 + 8) * N + col) = v1;
        }
    }
}

// ---------------------------------------------------------------------------
// RoPE in-place over rows of x[MR, D], rotary dim d == D (matches reference:
// kR uses D=d=64, qR uses D=d=1024 applied BEFORE the per-head reshape).
// ---------------------------------------------------------------------------
__global__ void rope_kernel(float* __restrict__ x, int D)
{
    const int pairs = D / 2;
    int idx = blockIdx.x * blockDim.x + threadIdx.x;
    if (idx >= MR * pairs) return;
    int row = idx / pairs;
    int i   = idx - row * pairs;
    int t   = row & (TT - 1);

    float theta = expf(-2.0f * (float)i / (float)D * 9.2103403719761836f);
    float ang   = (float)(t + 1) * theta;
    float sn, cs;
    sincosf(ang, &sn, &cs);

    float* p = x + (size_t)row * D + 2*i;
    float e = p[0], o = p[1];
    p[0] = e * cs - o * sn;
    p[1] = o * cs + e * sn;
}

// ---------------------------------------------------------------------------
// Causal flash attention, fp32. dqk = 128 (64 nope + 64 rope), dv = 64.
// One block = 64 query rows of one (batch, head). 256 threads.
// ---------------------------------------------------------------------------
#define AT_PAD 68

struct __align__(16) AttnSmem {
    float Qt[128][AT_PAD];
    float Kt[128][AT_PAD];
    float Ss[64][AT_PAD];
    float Vs[64][AT_PAD];
    float m[64];
    float l[64];
    float alpha[64];
};

__global__ __launch_bounds__(256, 2)
void attn_kernel()
{
    extern __shared__ char smem_raw[];
    AttnSmem& S = *reinterpret_cast<AttnSmem*>(smem_raw);

    const int tid = threadIdx.x;
    const int qt  = blockIdx.x;
    const int hh  = blockIdx.y;
    const int b   = blockIdx.z;
    const int base = b * TT + qt * 64;
    const float scale = 0.08838834764831845f;   // 128^-0.5

    for (int idx = tid; idx < 64*128; idx += 256) {
        int r = idx >> 7, d = idx & 127;
        float v = (d < 64)
            ? g_q [(size_t)(base + r)*1024 + hh*64 + d]
            : g_qr[(size_t)(base + r)*1024 + hh*64 + (d - 64)];
        S.Qt[d][r] = v * scale;
    }
    if (tid < 64) { S.m[tid] = -1e30f; S.l[tid] = 0.f; }

    const int tx = tid & 15, ty = tid >> 4;
    const int c0 = tx * 4,  r0 = ty * 4;

    float o[4][4];
#pragma unroll
    for (int i = 0; i < 4; i++)
#pragma unroll
        for (int j = 0; j < 4; j++) o[i][j] = 0.f;

    for (int kt = 0; kt <= qt; kt++) {
        __syncthreads();

        for (int idx = tid; idx < 64*128; idx += 256) {
            int c = idx >> 7, d = idx & 127;
            int krow = b * TT + kt*64 + c;
            S.Kt[d][c] = (d < 64)
                ? g_kv[(size_t)krow*2048 + hh*64 + d]
                : g_kr[(size_t)krow*64   + (d - 64)];
        }
        for (int idx = tid; idx < 64*64; idx += 256) {
            int j = idx >> 6, c = idx & 63;
            S.Vs[j][c] = g_kv[(size_t)(b*TT + kt*64 + j)*2048 + 1024 + hh*64 + c];
        }
        __syncthreads();

        float sa[4][4];
#pragma unroll
        for (int i = 0; i < 4; i++)
#pragma unroll
            for (int j = 0; j < 4; j++) sa[i][j] = 0.f;

#pragma unroll 4
        for (int d = 0; d < 128; d++) {
            float4 qa = *reinterpret_cast<const float4*>(&S.Qt[d][r0]);
            float4 kb = *reinterpret_cast<const float4*>(&S.Kt[d][c0]);
            float qv[4] = {qa.x, qa.y, qa.z, qa.w};
            float kv[4] = {kb.x, kb.y, kb.z, kb.w};
#pragma unroll
            for (int i = 0; i < 4; i++)
#pragma unroll
                for (int j = 0; j < 4; j++)
                    sa[i][j] += qv[i] * kv[j];
        }

        const bool diag = (kt == qt);
#pragma unroll
        for (int i = 0; i < 4; i++)
#pragma unroll
            for (int j = 0; j < 4; j++) {
                float v = sa[i][j];
                if (diag && (c0 + j) > (r0 + i)) v = -1e30f;
                S.Ss[r0 + i][c0 + j] = v;
            }
        __syncthreads();

        if (tid < 64) {
            int r = tid;
            float mo = S.m[r];
            float mx = mo;
#pragma unroll 8
            for (int j = 0; j < 64; j++) mx = fmaxf(mx, S.Ss[r][j]);
            float al = __expf(mo - mx);
            float sum = 0.f;
#pragma unroll 8
            for (int j = 0; j < 64; j++) {
                float p = __expf(S.Ss[r][j] - mx);
                S.Ss[r][j] = p;
                sum += p;
            }
            S.m[r] = mx;
            S.l[r] = S.l[r] * al + sum;
            S.alpha[r] = al;
        }
        __syncthreads();

#pragma unroll
        for (int i = 0; i < 4; i++) {
            float al = S.alpha[r0 + i];
#pragma unroll
            for (int j = 0; j < 4; j++) o[i][j] *= al;
        }
#pragma unroll 4
        for (int j = 0; j < 64; j++) {
            float4 vv = *reinterpret_cast<const float4*>(&S.Vs[j][c0]);
#pragma unroll
            for (int i = 0; i < 4; i++) {
                float p = S.Ss[r0 + i][j];
                o[i][0] += p * vv.x;
                o[i][1] += p * vv.y;
                o[i][2] += p * vv.z;
                o[i][3] += p * vv.w;
            }
        }
    }

#pragma unroll
    for (int i = 0; i < 4; i++) {
        float inv = 1.0f / S.l[r0 + i];
        float4 ov;
        ov.x = o[i][0] * inv;
        ov.y = o[i][1] * inv;
        ov.z = o[i][2] * inv;
        ov.w = o[i][3] * inv;
        *reinterpret_cast<float4*>(
            &g_att[(size_t)(base + r0 + i)*1024 + hh*64 + c0]) = ov;
    }
}

// ---------------------------------------------------------------------------
// Launch
// ---------------------------------------------------------------------------
extern "C" void kernel_launch(void* const* d_in, const int* in_sizes, int n_in,
                              void* d_out, int out_size)
{
    (void)in_sizes; (void)n_in; (void)out_size;
    const float* x   = (const float*)d_in[0];
    const float* w1  = (const float*)d_in[1];
    const float* b1  = (const float*)d_in[2];
    const float* wkr = (const float*)d_in[3];
    const float* bkr = (const float*)d_in[4];
    const float* wqr = (const float*)d_in[5];
    const float* bqr = (const float*)d_in[6];
    const float* wkv = (const float*)d_in[7];
    const float* bkv = (const float*)d_in[8];
    const float* wq  = (const float*)d_in[9];
    const float* bq  = (const float*)d_in[10];
    const float* wo  = (const float*)d_in[11];
    const float* bo  = (const float*)d_in[12];
    float* out = (float*)d_out;

    float *h_, *kr_, *qr_, *kv_, *q_, *att_;
    cudaGetSymbolAddress((void**)&h_,   g_h);
    cudaGetSymbolAddress((void**)&kr_,  g_kr);
    cudaGetSymbolAddress((void**)&qr_,  g_qr);
    cudaGetSymbolAddress((void**)&kv_,  g_kv);
    cudaGetSymbolAddress((void**)&q_,   g_q);
    cudaGetSymbolAddress((void**)&att_, g_att);

    // 1) h = x @ w1 + b1                 [4096,1024] x [1024,1024]
    gemm_tf32<128,128><<<dim3(8, 32), 256>>>(MR, 1024, 1024, x, 1024, w1, b1, h_);

    // 2) kr = rope(h @ wkr + bkr, 64)    [4096,1024] x [1024,64]
    gemm_tf32<128,64><<<dim3(1, 32), 256>>>(MR, 64, 1024, h_, 1024, wkr, bkr, kr_);
    {
        int n = MR * (64/2);
        rope_kernel<<<(n + 255)/256, 256>>>(kr_, 64);
    }

    // 3) qr = rope(h @ wqr + bqr, 1024)  [4096,1024] x [1024,1024]
    gemm_tf32<128,128><<<dim3(8, 32), 256>>>(MR, 1024, 1024, h_, 1024, wqr, bqr, qr_);
    {
        int n = MR * (1024/2);
        rope_kernel<<<(n + 255)/256, 256>>>(qr_, 1024);
    }

    // 4) kv = cKV @ wkv + bkv            [4096,512] x [512,2048]
    gemm_tf32<128,128><<<dim3(16, 32), 256>>>(MR, 2048, 512, h_, 1024, wkv, bkv, kv_);

    // 5) q = cq @ wq + bq                [4096,512] x [512,1024]
    gemm_tf32<128,128><<<dim3(8, 32), 256>>>(MR, 1024, 512, h_ + 512, 1024, wq, bq, q_);

    // 6) causal attention -> g_att
    cudaFuncSetAttribute(attn_kernel,
                         cudaFuncAttributeMaxDynamicSharedMemorySize,
                         (int)sizeof(AttnSmem));
    attn_kernel<<<dim3(TT/64, NH, BB), 256, sizeof(AttnSmem)>>>();

    // 7) out = att @ wo + bo             [4096,1024] x [1024,1024]
    gemm_tf32<128,128><<<dim3(8, 32), 256>>>(MR, 1024, 1024, att_, 1024, wo, bo, out);
}

// round 3
// speedup vs baseline: 1.9675x; 1.3280x over previous
#include <cuda_runtime.h>
#include <math.h>
#include <stdint.h>

// Problem constants
#define BB   2
#define TT   2048
#define CC   1024
#define NH   16
#define LAT  512
#define DHR  64
#define MR   (BB*TT)        // 4096 rows

// ---------------------------------------------------------------------------
// Scratch
// ---------------------------------------------------------------------------
__device__ float g_h  [MR * 1024];
__device__ float g_kr [MR * 64];
__device__ float g_qr [MR * 1024];
__device__ float g_kv [MR * 2048];   // k cols 0..1023, v cols 1024..2047
__device__ float g_q  [MR * 1024];
__device__ float g_att[MR * 1024];

// ---------------------------------------------------------------------------
// helpers
// ---------------------------------------------------------------------------
__device__ __forceinline__ uint32_t f2tf(float f) {
    uint32_t u;
    asm("cvt.rna.tf32.f32 %0, %1;" : "=r"(u) : "f"(f));
    return u;
}

__device__ __forceinline__ void mma8(float* c,
                                     uint32_t a0, uint32_t a1, uint32_t a2, uint32_t a3,
                                     uint32_t b0, uint32_t b1) {
    asm volatile(
        "mma.sync.aligned.m16n8k8.row.col.f32.tf32.tf32.f32 "
        "{%0,%1,%2,%3},{%4,%5,%6,%7},{%8,%9},{%0,%1,%2,%3};"
        : "+f"(c[0]), "+f"(c[1]), "+f"(c[2]), "+f"(c[3])
        : "r"(a0), "r"(a1), "r"(a2), "r"(a3), "r"(b0), "r"(b1));
}

__device__ __forceinline__ uint32_t sptr(const void* p) {
    return (uint32_t)__cvta_generic_to_shared(p);
}
__device__ __forceinline__ void cp16(uint32_t dst, const void* src) {
    asm volatile("cp.async.cg.shared.global [%0], [%1], 16;" :: "r"(dst), "l"(src));
}
__device__ __forceinline__ void cp_commit() {
    asm volatile("cp.async.commit_group;");
}
template<int N> __device__ __forceinline__ void cp_wait() {
    asm volatile("cp.async.wait_group %0;" :: "n"(N));
}

// ---------------------------------------------------------------------------
// Split-tf32 (3-MMA, ~fp32-accurate) GEMM + bias: C = A@B + bias
// 2-stage cp.async pipeline, fp32 smem, split at fragment load:
//   hi = cvt.rna.tf32(x), lo = x - hi  (exact; residual ~2^-21)
// 8 warps (4x2), warp tile (BM/4) x (BN/2). Requires M%BM==0,N%BN==0,K%32==0.
// ---------------------------------------------------------------------------
template<int BM, int BN>
__global__ __launch_bounds__(256, 2)
void gemm_3x(int M, int N, int K,
             const float* __restrict__ A, int lda,
             const float* __restrict__ B,
             const float* __restrict__ bias,
             float* __restrict__ C)
{
    constexpr int WM   = BM / 4;
    constexpr int WN   = BN / 2;
    constexpr int MT   = WM / 16;
    constexpr int NT   = WN / 8;
    constexpr int BSTR = BN + 8;
    constexpr int NA   = (BM * 8) / 256;          // float4 A loads / thread / stage
    constexpr int NB   = (BN * 8) / 256;          // float4 B loads / thread / stage
    constexpr int ASZ  = BM * 32;
    constexpr int BSZ  = 32 * BSTR;

    extern __shared__ float sm[];
    float* Asm = sm;              // [2][ASZ]
    float* Bsm = sm + 2 * ASZ;    // [2][BSZ]

    const int tid  = threadIdx.x;
    const int lane = tid & 31;
    const int warp = tid >> 5;
    const int g    = lane >> 2;
    const int t    = lane & 3;
    const int wm   = warp >> 1;
    const int wn   = warp & 1;
    const int bRow = blockIdx.y * BM;
    const int bCol = blockIdx.x * BN;

    float acc[MT][NT][4];
#pragma unroll
    for (int mt = 0; mt < MT; mt++)
#pragma unroll
        for (int nt = 0; nt < NT; nt++)
#pragma unroll
            for (int i = 0; i < 4; i++) acc[mt][nt][i] = 0.f;

    auto issue = [&](int k0, int s) {
        float* as = Asm + s * ASZ;
        float* bs = Bsm + s * BSZ;
#pragma unroll
        for (int i = 0; i < NA; i++) {
            int idx = tid + i * 256;
            int r = idx >> 3, c4 = idx & 7;
            cp16(sptr(as + r * 32 + ((c4 ^ (r & 7)) << 2)),
                 A + (size_t)(bRow + r) * lda + k0 + 4 * c4);
        }
#pragma unroll
        for (int i = 0; i < NB; i++) {
            int idx = tid + i * 256;
            int r = idx / (BN / 4), c4 = idx % (BN / 4);
            cp16(sptr(bs + r * BSTR + 4 * c4),
                 B + (size_t)(k0 + r) * N + bCol + 4 * c4);
        }
        cp_commit();
    };

    const int iters = K / 32;
    issue(0, 0);

    for (int it = 0; it < iters; it++) {
        const int cur = it & 1;
        if (it + 1 < iters) { issue((it + 1) * 32, cur ^ 1); cp_wait<1>(); }
        else                { cp_wait<0>(); }
        __syncthreads();

        const float* as = Asm + cur * ASZ;
        const float* bs = Bsm + cur * BSZ;

#pragma unroll
        for (int kk = 0; kk < 4; kk++) {
            uint32_t ah[MT][4], al[MT][4];
#pragma unroll
            for (int mt = 0; mt < MT; mt++) {
                int r0 = wm * WM + mt * 16 + g;
                int r1 = r0 + 8;
                int s0 = (2 * kk) ^ g;
                int s1 = (2 * kk + 1) ^ g;
                float x0 = as[r0 * 32 + (s0 << 2) + t];
                float x1 = as[r1 * 32 + (s0 << 2) + t];
                float x2 = as[r0 * 32 + (s1 << 2) + t];
                float x3 = as[r1 * 32 + (s1 << 2) + t];
                ah[mt][0] = f2tf(x0); al[mt][0] = __float_as_uint(x0 - __uint_as_float(ah[mt][0]));
                ah[mt][1] = f2tf(x1); al[mt][1] = __float_as_uint(x1 - __uint_as_float(ah[mt][1]));
                ah[mt][2] = f2tf(x2); al[mt][2] = __float_as_uint(x2 - __uint_as_float(ah[mt][2]));
                ah[mt][3] = f2tf(x3); al[mt][3] = __float_as_uint(x3 - __uint_as_float(ah[mt][3]));
            }
#pragma unroll
            for (int nt = 0; nt < NT; nt++) {
                int nb = wn * WN + nt * 8 + g;
                float b0f = bs[(kk * 8 + t)     * BSTR + nb];
                float b1f = bs[(kk * 8 + t + 4) * BSTR + nb];
                uint32_t bh0 = f2tf(b0f), bh1 = f2tf(b1f);
                uint32_t bl0 = __float_as_uint(b0f - __uint_as_float(bh0));
                uint32_t bl1 = __float_as_uint(b1f - __uint_as_float(bh1));
#pragma unroll
                for (int mt = 0; mt < MT; mt++) {
                    mma8(acc[mt][nt], ah[mt][0], ah[mt][1], ah[mt][2], ah[mt][3], bh0, bh1);
                    mma8(acc[mt][nt], ah[mt][0], ah[mt][1], ah[mt][2], ah[mt][3], bl0, bl1);
                    mma8(acc[mt][nt], al[mt][0], al[mt][1], al[mt][2], al[mt][3], bh0, bh1);
                }
            }
        }
        __syncthreads();
    }

#pragma unroll
    for (int mt = 0; mt < MT; mt++) {
        int r0 = bRow + wm * WM + mt * 16 + g;
#pragma unroll
        for (int nt = 0; nt < NT; nt++) {
            int col = bCol + wn * WN + nt * 8 + 2 * t;
            float bx = bias[col], by = bias[col + 1];
            float2 v0 = {acc[mt][nt][0] + bx, acc[mt][nt][1] + by};
            float2 v1 = {acc[mt][nt][2] + bx, acc[mt][nt][3] + by};
            *reinterpret_cast<float2*>(C + (size_t)r0 * N + col)       = v0;
            *reinterpret_cast<float2*>(C + (size_t)(r0 + 8) * N + col) = v1;
        }
    }
}

// ---------------------------------------------------------------------------
// RoPE (unchanged)
// ---------------------------------------------------------------------------
__global__ void rope_kernel(float* __restrict__ x, int D)
{
    const int pairs = D / 2;
    int idx = blockIdx.x * blockDim.x + threadIdx.x;
    if (idx >= MR * pairs) return;
    int row = idx / pairs;
    int i   = idx - row * pairs;
    int t   = row & (TT - 1);

    float theta = expf(-2.0f * (float)i / (float)D * 9.2103403719761836f);
    float ang   = (float)(t + 1) * theta;
    float sn, cs;
    sincosf(ang, &sn, &cs);

    float* p = x + (size_t)row * D + 2*i;
    float e = p[0], o = p[1];
    p[0] = e * cs - o * sn;
    p[1] = o * cs + e * sn;
}

// ---------------------------------------------------------------------------
// Tensor-core causal flash attention (tf32). dqk=128, dv=64.
// Block: 128 q-rows of one (b,h), 256 threads (8 warps, warp = 16 rows).
// smem: Qs[128][136] (tf32, pre-scaled), Ks[128][72] ([d][key], tf32),
//       Vs[64][72] ([key][dv], tf32), Ps[128][72] (tf32).
// Online softmax entirely in registers (4-lane shfl row groups).
// ---------------------------------------------------------------------------
#define QSTR 136
#define KSTR 72

struct AttnSm {
    float Qs[128 * QSTR];
    float Ks[128 * KSTR];
    float Vs[64 * KSTR];
    float Ps[128 * KSTR];
};

__global__ __launch_bounds__(256, 1)
void attn_tc_kernel()
{
    extern __shared__ char smraw[];
    AttnSm& S = *reinterpret_cast<AttnSm*>(smraw);

    const int tid  = threadIdx.x;
    const int lane = tid & 31;
    const int warp = tid >> 5;
    const int g    = lane >> 2;
    const int t    = lane & 3;
    const int qt   = blockIdx.x;     // 0..15
    const int hh   = blockIdx.y;
    const int b    = blockIdx.z;
    const int rowBase = b * TT + qt * 128;
    const float scale = 0.08838834764831845f;   // 128^-0.5

    // --- load Q tile once: Qs[r][d], tf32, pre-scaled -----------------------
    for (int i = 0; i < 16; i++) {
        int idx = tid + i * 256;
        int r = idx >> 5, d4 = idx & 31;
        int d = 4 * d4;
        float4 v = (d < 64)
            ? *reinterpret_cast<const float4*>(&g_q [(size_t)(rowBase + r) * 1024 + hh * 64 + d])
            : *reinterpret_cast<const float4*>(&g_qr[(size_t)(rowBase + r) * 1024 + hh * 64 + (d - 64)]);
        float4 s;
        s.x = __uint_as_float(f2tf(v.x * scale));
        s.y = __uint_as_float(f2tf(v.y * scale));
        s.z = __uint_as_float(f2tf(v.z * scale));
        s.w = __uint_as_float(f2tf(v.w * scale));
        *reinterpret_cast<float4*>(&S.Qs[r * QSTR + d]) = s;
    }

    const int rloc0 = warp * 16 + g;     // warp-owned rows
    float m0 = -1e30f, m1 = -1e30f, l0 = 0.f, l1 = 0.f;
    float o[8][4];
#pragma unroll
    for (int nt = 0; nt < 8; nt++)
#pragma unroll
        for (int i = 0; i < 4; i++) o[nt][i] = 0.f;

    const int nkt = 2 * qt + 2;
    for (int j = 0; j < nkt; j++) {
        const int k0 = j * 64;
        __syncthreads();   // Qs ready (j=0) / previous PV done

        // --- load K tile transposed: Ks[d][c], tf32 -------------------------
#pragma unroll
        for (int i = 0; i < 8; i++) {
            int idx = tid + i * 256;
            int c = idx & 63, d4 = idx >> 6;
            int d = 4 * d4;
            int krow = b * TT + k0 + c;
            float4 v = (d < 64)
                ? *reinterpret_cast<const float4*>(&g_kv[(size_t)krow * 2048 + hh * 64 + d])
                : *reinterpret_cast<const float4*>(&g_kr[(size_t)krow * 64 + (d - 64)]);
            S.Ks[(d + 0) * KSTR + c] = __uint_as_float(f2tf(v.x));
            S.Ks[(d + 1) * KSTR + c] = __uint_as_float(f2tf(v.y));
            S.Ks[(d + 2) * KSTR + c] = __uint_as_float(f2tf(v.z));
            S.Ks[(d + 3) * KSTR + c] = __uint_as_float(f2tf(v.w));
        }
        // --- load V tile: Vs[key][dv], tf32 ---------------------------------
#pragma unroll
        for (int i = 0; i < 4; i++) {
            int idx = tid + i * 256;
            int r = idx >> 4, c4 = idx & 15;
            float4 v = *reinterpret_cast<const float4*>(
                &g_kv[(size_t)(b * TT + k0 + r) * 2048 + 1024 + hh * 64 + 4 * c4]);
            float4 s;
            s.x = __uint_as_float(f2tf(v.x));
            s.y = __uint_as_float(f2tf(v.y));
            s.z = __uint_as_float(f2tf(v.z));
            s.w = __uint_as_float(f2tf(v.w));
            *reinterpret_cast<float4*>(&S.Vs[r * KSTR + 4 * c4]) = s;
        }
        __syncthreads();

        // --- S = Q @ K^T ----------------------------------------------------
        float sc[8][4];
#pragma unroll
        for (int nt = 0; nt < 8; nt++)
#pragma unroll
            for (int i = 0; i < 4; i++) sc[nt][i] = 0.f;

#pragma unroll
        for (int ks = 0; ks < 16; ks++) {
            uint32_t a0 = __float_as_uint(S.Qs[(rloc0)     * QSTR + ks * 8 + t]);
            uint32_t a1 = __float_as_uint(S.Qs[(rloc0 + 8) * QSTR + ks * 8 + t]);
            uint32_t a2 = __float_as_uint(S.Qs[(rloc0)     * QSTR + ks * 8 + t + 4]);
            uint32_t a3 = __float_as_uint(S.Qs[(rloc0 + 8) * QSTR + ks * 8 + t + 4]);
#pragma unroll
            for (int nt = 0; nt < 8; nt++) {
                uint32_t b0 = __float_as_uint(S.Ks[(ks * 8 + t)     * KSTR + nt * 8 + g]);
                uint32_t b1 = __float_as_uint(S.Ks[(ks * 8 + t + 4) * KSTR + nt * 8 + g]);
                mma8(sc[nt], a0, a1, a2, a3, b0, b1);
            }
        }

        // --- causal mask (only last two k-tiles can cross the diagonal) -----
        if (j >= 2 * qt) {
            int rg0 = qt * 128 + rloc0;
#pragma unroll
            for (int nt = 0; nt < 8; nt++) {
                int cg = k0 + nt * 8 + 2 * t;
                if (cg     > rg0)     sc[nt][0] = -1e30f;
                if (cg + 1 > rg0)     sc[nt][1] = -1e30f;
                if (cg     > rg0 + 8) sc[nt][2] = -1e30f;
                if (cg + 1 > rg0 + 8) sc[nt][3] = -1e30f;
            }
        }

        // --- online softmax in registers ------------------------------------
        float mx0 = -1e30f, mx1 = -1e30f;
#pragma unroll
        for (int nt = 0; nt < 8; nt++) {
            mx0 = fmaxf(mx0, fmaxf(sc[nt][0], sc[nt][1]));
            mx1 = fmaxf(mx1, fmaxf(sc[nt][2], sc[nt][3]));
        }
        mx0 = fmaxf(mx0, __shfl_xor_sync(0xffffffffu, mx0, 1));
        mx0 = fmaxf(mx0, __shfl_xor_sync(0xffffffffu, mx0, 2));
        mx1 = fmaxf(mx1, __shfl_xor_sync(0xffffffffu, mx1, 1));
        mx1 = fmaxf(mx1, __shfl_xor_sync(0xffffffffu, mx1, 2));

        float mn0 = fmaxf(m0, mx0), mn1 = fmaxf(m1, mx1);
        float al0 = __expf(m0 - mn0), al1 = __expf(m1 - mn1);
        m0 = mn0; m1 = mn1;

        float sum0 = 0.f, sum1 = 0.f;
#pragma unroll
        for (int nt = 0; nt < 8; nt++) {
            float p0 = __expf(sc[nt][0] - mn0);
            float p1 = __expf(sc[nt][1] - mn0);
            float p2 = __expf(sc[nt][2] - mn1);
            float p3 = __expf(sc[nt][3] - mn1);
            sum0 += p0 + p1; sum1 += p2 + p3;
            float2 w0 = {__uint_as_float(f2tf(p0)), __uint_as_float(f2tf(p1))};
            float2 w1 = {__uint_as_float(f2tf(p2)), __uint_as_float(f2tf(p3))};
            *reinterpret_cast<float2*>(&S.Ps[(rloc0)     * KSTR + nt * 8 + 2 * t]) = w0;
            *reinterpret_cast<float2*>(&S.Ps[(rloc0 + 8) * KSTR + nt * 8 + 2 * t]) = w1;
        }
        sum0 += __shfl_xor_sync(0xffffffffu, sum0, 1);
        sum0 += __shfl_xor_sync(0xffffffffu, sum0, 2);
        sum1 += __shfl_xor_sync(0xffffffffu, sum1, 1);
        sum1 += __shfl_xor_sync(0xffffffffu, sum1, 2);
        l0 = l0 * al0 + sum0;
        l1 = l1 * al1 + sum1;

#pragma unroll
        for (int nt = 0; nt < 8; nt++) {
            o[nt][0] *= al0; o[nt][1] *= al0;
            o[nt][2] *= al1; o[nt][3] *= al1;
        }
        __syncwarp();   // Ps exchange is intra-warp only

        // --- O += P @ V ------------------------------------------------------
#pragma unroll
        for (int ks = 0; ks < 8; ks++) {
            uint32_t a0 = __float_as_uint(S.Ps[(rloc0)     * KSTR + ks * 8 + t]);
            uint32_t a1 = __float_as_uint(S.Ps[(rloc0 + 8) * KSTR + ks * 8 + t]);
            uint32_t a2 = __float_as_uint(S.Ps[(rloc0)     * KSTR + ks * 8 + t + 4]);
            uint32_t a3 = __float_as_uint(S.Ps[(rloc0 + 8) * KSTR + ks * 8 + t + 4]);
#pragma unroll
            for (int nt = 0; nt < 8; nt++) {
                uint32_t b0 = __float_as_uint(S.Vs[(ks * 8 + t)     * KSTR + nt * 8 + g]);
                uint32_t b1 = __float_as_uint(S.Vs[(ks * 8 + t + 4) * KSTR + nt * 8 + g]);
                mma8(o[nt], a0, a1, a2, a3, b0, b1);
            }
        }
    }

    // --- finalize + store ---------------------------------------------------
    float inv0 = 1.0f / l0, inv1 = 1.0f / l1;
    int rg = rowBase + rloc0;
#pragma unroll
    for (int nt = 0; nt < 8; nt++) {
        int col = hh * 64 + nt * 8 + 2 * t;
        float2 v0 = {o[nt][0] * inv0, o[nt][1] * inv0};
        float2 v1 = {o[nt][2] * inv1, o[nt][3] * inv1};
        *reinterpret_cast<float2*>(&g_att[(size_t)rg       * 1024 + col]) = v0;
        *reinterpret_cast<float2*>(&g_att[(size_t)(rg + 8) * 1024 + col]) = v1;
    }
}

// ---------------------------------------------------------------------------
// Launch
// ---------------------------------------------------------------------------
extern "C" void kernel_launch(void* const* d_in, const int* in_sizes, int n_in,
                              void* d_out, int out_size)
{
    (void)in_sizes; (void)n_in; (void)out_size;
    const float* x   = (const float*)d_in[0];
    const float* w1  = (const float*)d_in[1];
    const float* b1  = (const float*)d_in[2];
    const float* wkr = (const float*)d_in[3];
    const float* bkr = (const float*)d_in[4];
    const float* wqr = (const float*)d_in[5];
    const float* bqr = (const float*)d_in[6];
    const float* wkv = (const float*)d_in[7];
    const float* bkv = (const float*)d_in[8];
    const float* wq  = (const float*)d_in[9];
    const float* bq  = (const float*)d_in[10];
    const float* wo  = (const float*)d_in[11];
    const float* bo  = (const float*)d_in[12];
    float* out = (float*)d_out;

    float *h_, *kr_, *qr_, *kv_, *q_, *att_;
    cudaGetSymbolAddress((void**)&h_,   g_h);
    cudaGetSymbolAddress((void**)&kr_,  g_kr);
    cudaGetSymbolAddress((void**)&qr_,  g_qr);
    cudaGetSymbolAddress((void**)&kv_,  g_kv);
    cudaGetSymbolAddress((void**)&q_,   g_q);
    cudaGetSymbolAddress((void**)&att_, g_att);

    const int SM128 = (2 * 128 * 32 + 2 * 32 * 136) * 4;   // 67584
    const int SM64  = (2 * 128 * 32 + 2 * 32 * 72)  * 4;   // 51200
    const int SMAT  = (int)sizeof(AttnSm);                  // 161792
    cudaFuncSetAttribute(gemm_3x<128,128>, cudaFuncAttributeMaxDynamicSharedMemorySize, SM128);
    cudaFuncSetAttribute(gemm_3x<128,64>,  cudaFuncAttributeMaxDynamicSharedMemorySize, SM64);
    cudaFuncSetAttribute(attn_tc_kernel,   cudaFuncAttributeMaxDynamicSharedMemorySize, SMAT);

    // 1) h = x @ w1 + b1
    gemm_3x<128,128><<<dim3(8, 32), 256, SM128>>>(MR, 1024, 1024, x, 1024, w1, b1, h_);

    // 2) kr = rope(h @ wkr + bkr, 64)
    gemm_3x<128,64><<<dim3(1, 32), 256, SM64>>>(MR, 64, 1024, h_, 1024, wkr, bkr, kr_);
    rope_kernel<<<(MR * 32 + 255) / 256, 256>>>(kr_, 64);

    // 3) qr = rope(h @ wqr + bqr, 1024)
    gemm_3x<128,128><<<dim3(8, 32), 256, SM128>>>(MR, 1024, 1024, h_, 1024, wqr, bqr, qr_);
    rope_kernel<<<(MR * 512 + 255) / 256, 256>>>(qr_, 1024);

    // 4) kv = cKV @ wkv + bkv
    gemm_3x<128,128><<<dim3(16, 32), 256, SM128>>>(MR, 2048, 512, h_, 1024, wkv, bkv, kv_);

    // 5) q = cq @ wq + bq
    gemm_3x<128,128><<<dim3(8, 32), 256, SM128>>>(MR, 1024, 512, h_ + 512, 1024, wq, bq, q_);

    // 6) attention
    attn_tc_kernel<<<dim3(16, NH, BB), 256, SMAT>>>();

    // 7) out = att @ wo + bo
    gemm_3x<128,128><<<dim3(8, 32), 256, SM128>>>(MR, 1024, 1024, att_, 1024, wo, bo, out);
}

// round 4
// speedup vs baseline: 2.5081x; 1.2748x over previous
#include <cuda_runtime.h>
#include <math.h>
#include <stdint.h>

// Problem constants
#define BB   2
#define TT   2048
#define CC   1024
#define NH   16
#define LAT  512
#define DHR  64
#define MR   (BB*TT)        // 4096 rows

// ---------------------------------------------------------------------------
// Scratch
// ---------------------------------------------------------------------------
__device__ float g_h  [MR * 1024];
__device__ float g_kr [MR * 64];
__device__ float g_qr [MR * 1024];
__device__ float g_kv [MR * 2048];   // k cols 0..1023, v cols 1024..2047
__device__ float g_q  [MR * 1024];
__device__ float g_att[MR * 1024];

// ---------------------------------------------------------------------------
// helpers
// ---------------------------------------------------------------------------
__device__ __forceinline__ uint32_t f2tf(float f) {
    uint32_t u;
    asm("cvt.rna.tf32.f32 %0, %1;" : "=r"(u) : "f"(f));
    return u;
}

// tf32 m16n8k8 (attention)
__device__ __forceinline__ void mma8(float* c,
                                     uint32_t a0, uint32_t a1, uint32_t a2, uint32_t a3,
                                     uint32_t b0, uint32_t b1) {
    asm volatile(
        "mma.sync.aligned.m16n8k8.row.col.f32.tf32.tf32.f32 "
        "{%0,%1,%2,%3},{%4,%5,%6,%7},{%8,%9},{%0,%1,%2,%3};"
        : "+f"(c[0]), "+f"(c[1]), "+f"(c[2]), "+f"(c[3])
        : "r"(a0), "r"(a1), "r"(a2), "r"(a3), "r"(b0), "r"(b1));
}

// bf16 m16n8k16 (projection GEMMs, split-bf16 3x scheme)
__device__ __forceinline__ void mma16(float* c, const uint32_t* a,
                                      uint32_t b0, uint32_t b1) {
    asm volatile(
        "mma.sync.aligned.m16n8k16.row.col.f32.bf16.bf16.f32 "
        "{%0,%1,%2,%3},{%4,%5,%6,%7},{%8,%9},{%0,%1,%2,%3};"
        : "+f"(c[0]), "+f"(c[1]), "+f"(c[2]), "+f"(c[3])
        : "r"(a[0]), "r"(a[1]), "r"(a[2]), "r"(a[3]), "r"(b0), "r"(b1));
}

// Dekker bf16 split of a k-consecutive pair (x = even k, y = odd k).
// hi = bf16x2(x,y) (x in low half), lo = bf16x2 of exact residuals.
__device__ __forceinline__ void split2(float x, float y, uint32_t& hi, uint32_t& lo) {
    uint32_t h, l;
    asm("cvt.rn.bf16x2.f32 %0, %1, %2;" : "=r"(h) : "f"(y), "f"(x));
    float hx = __uint_as_float(h << 16);
    float hy = __uint_as_float(h & 0xffff0000u);
    float lx = x - hx;    // exact (Sterbenz)
    float ly = y - hy;
    asm("cvt.rn.bf16x2.f32 %0, %1, %2;" : "=r"(l) : "f"(ly), "f"(lx));
    hi = h; lo = l;
}

__device__ __forceinline__ uint32_t sptr(const void* p) {
    return (uint32_t)__cvta_generic_to_shared(p);
}
__device__ __forceinline__ void cp16(uint32_t dst, const void* src) {
    asm volatile("cp.async.cg.shared.global [%0], [%1], 16;" :: "r"(dst), "l"(src));
}
__device__ __forceinline__ void cp_commit() {
    asm volatile("cp.async.commit_group;");
}
template<int N> __device__ __forceinline__ void cp_wait() {
    asm volatile("cp.async.wait_group %0;" :: "n"(N));
}

// ---------------------------------------------------------------------------
// Split-bf16 (3-MMA, ~fp32-accurate) GEMM + bias: C = A@B + bias
// 2-stage cp.async pipeline, fp32 smem; Dekker bf16 split at fragment load.
// Error per GEMM ~1e-5 (only al*bl dropped, ~2^-18).
// 8 warps (4x2), warp tile (BM/4) x (BN/2). Requires M%BM==0,N%BN==0,K%32==0.
// ---------------------------------------------------------------------------
template<int BM, int BN>
__global__ __launch_bounds__(256, 2)
void gemm_3x(int M, int N, int K,
             const float* __restrict__ A, int lda,
             const float* __restrict__ B,
             const float* __restrict__ bias,
             float* __restrict__ C)
{
    constexpr int WM   = BM / 4;
    constexpr int WN   = BN / 2;
    constexpr int MT   = WM / 16;
    constexpr int NT   = WN / 8;
    constexpr int BSTR = BN + 8;
    constexpr int NA   = (BM * 8) / 256;
    constexpr int NB   = (BN * 8) / 256;
    constexpr int ASZ  = BM * 32;
    constexpr int BSZ  = 32 * BSTR;

    extern __shared__ float sm[];
    float* Asm = sm;              // [2][ASZ]
    float* Bsm = sm + 2 * ASZ;    // [2][BSZ]

    const int tid  = threadIdx.x;
    const int lane = tid & 31;
    const int warp = tid >> 5;
    const int g    = lane >> 2;
    const int t    = lane & 3;
    const int wm   = warp >> 1;
    const int wn   = warp & 1;
    const int bRow = blockIdx.y * BM;
    const int bCol = blockIdx.x * BN;

    float acc[MT][NT][4];
#pragma unroll
    for (int mt = 0; mt < MT; mt++)
#pragma unroll
        for (int nt = 0; nt < NT; nt++)
#pragma unroll
            for (int i = 0; i < 4; i++) acc[mt][nt][i] = 0.f;

    auto issue = [&](int k0, int s) {
        float* as = Asm + s * ASZ;
        float* bs = Bsm + s * BSZ;
#pragma unroll
        for (int i = 0; i < NA; i++) {
            int idx = tid + i * 256;
            int r = idx >> 3, c4 = idx & 7;
            cp16(sptr(as + r * 32 + ((c4 ^ (r & 7)) << 2)),
                 A + (size_t)(bRow + r) * lda + k0 + 4 * c4);
        }
#pragma unroll
        for (int i = 0; i < NB; i++) {
            int idx = tid + i * 256;
            int r = idx / (BN / 4), c4 = idx % (BN / 4);
            cp16(sptr(bs + r * BSTR + 4 * c4),
                 B + (size_t)(k0 + r) * N + bCol + 4 * c4);
        }
        cp_commit();
    };

    const int iters = K / 32;
    issue(0, 0);

    for (int it = 0; it < iters; it++) {
        const int cur = it & 1;
        if (it + 1 < iters) { issue((it + 1) * 32, cur ^ 1); cp_wait<1>(); }
        else                { cp_wait<0>(); }
        __syncthreads();

        const float* as = Asm + cur * ASZ;
        const float* bs = Bsm + cur * BSZ;

        // two k16 steps per 32-wide k-tile
#pragma unroll
        for (int s = 0; s < 2; s++) {
            uint32_t ah[MT][4], al[MT][4];
            const int g0  = 4 * s + (t >> 1);      // float4 group of k=16s+2t
            const int g1  = g0 + 2;                // group of k+8
            const int off = (2 * t) & 3;
            const int sw0 = ((g0 ^ g) << 2) + off; // row&7 == g for all warp rows
            const int sw1 = ((g1 ^ g) << 2) + off;
#pragma unroll
            for (int mt = 0; mt < MT; mt++) {
                int r0 = wm * WM + mt * 16 + g;
                int r1 = r0 + 8;
                float2 x00 = *reinterpret_cast<const float2*>(&as[r0 * 32 + sw0]);
                float2 x10 = *reinterpret_cast<const float2*>(&as[r1 * 32 + sw0]);
                float2 x01 = *reinterpret_cast<const float2*>(&as[r0 * 32 + sw1]);
                float2 x11 = *reinterpret_cast<const float2*>(&as[r1 * 32 + sw1]);
                split2(x00.x, x00.y, ah[mt][0], al[mt][0]);
                split2(x10.x, x10.y, ah[mt][1], al[mt][1]);
                split2(x01.x, x01.y, ah[mt][2], al[mt][2]);
                split2(x11.x, x11.y, ah[mt][3], al[mt][3]);
            }
            const int kb = 16 * s + 2 * t;
#pragma unroll
            for (int nt = 0; nt < NT; nt++) {
                int nb = wn * WN + nt * 8 + g;
                float b00 = bs[(kb)     * BSTR + nb];
                float b01 = bs[(kb + 1) * BSTR + nb];
                float b10 = bs[(kb + 8) * BSTR + nb];
                float b11 = bs[(kb + 9) * BSTR + nb];
                uint32_t bh0, bl0, bh1, bl1;
                split2(b00, b01, bh0, bl0);
                split2(b10, b11, bh1, bl1);
#pragma unroll
                for (int mt = 0; mt < MT; mt++) {
                    mma16(acc[mt][nt], ah[mt], bh0, bh1);
                    mma16(acc[mt][nt], ah[mt], bl0, bl1);
                    mma16(acc[mt][nt], al[mt], bh0, bh1);
                }
            }
        }
        __syncthreads();
    }

#pragma unroll
    for (int mt = 0; mt < MT; mt++) {
        int r0 = bRow + wm * WM + mt * 16 + g;
#pragma unroll
        for (int nt = 0; nt < NT; nt++) {
            int col = bCol + wn * WN + nt * 8 + 2 * t;
            float bx = bias[col], by = bias[col + 1];
            float2 v0 = {acc[mt][nt][0] + bx, acc[mt][nt][1] + by};
            float2 v1 = {acc[mt][nt][2] + bx, acc[mt][nt][3] + by};
            *reinterpret_cast<float2*>(C + (size_t)r0 * N + col)       = v0;
            *reinterpret_cast<float2*>(C + (size_t)(r0 + 8) * N + col) = v1;
        }
    }
}

// ---------------------------------------------------------------------------
// RoPE (unchanged)
// ---------------------------------------------------------------------------
__global__ void rope_kernel(float* __restrict__ x, int D)
{
    const int pairs = D / 2;
    int idx = blockIdx.x * blockDim.x + threadIdx.x;
    if (idx >= MR * pairs) return;
    int row = idx / pairs;
    int i   = idx - row * pairs;
    int t   = row & (TT - 1);

    float theta = expf(-2.0f * (float)i / (float)D * 9.2103403719761836f);
    float ang   = (float)(t + 1) * theta;
    float sn, cs;
    sincosf(ang, &sn, &cs);

    float* p = x + (size_t)row * D + 2*i;
    float e = p[0], o = p[1];
    p[0] = e * cs - o * sn;
    p[1] = o * cs + e * sn;
}

// ---------------------------------------------------------------------------
// Tensor-core causal flash attention (tf32). dqk=128, dv=64. (unchanged)
// ---------------------------------------------------------------------------
#define QSTR 136
#define KSTR 72

struct AttnSm {
    float Qs[128 * QSTR];
    float Ks[128 * KSTR];
    float Vs[64 * KSTR];
    float Ps[128 * KSTR];
};

__global__ __launch_bounds__(256, 1)
void attn_tc_kernel()
{
    extern __shared__ char smraw[];
    AttnSm& S = *reinterpret_cast<AttnSm*>(smraw);

    const int tid  = threadIdx.x;
    const int lane = tid & 31;
    const int warp = tid >> 5;
    const int g    = lane >> 2;
    const int t    = lane & 3;
    const int qt   = blockIdx.x;
    const int hh   = blockIdx.y;
    const int b    = blockIdx.z;
    const int rowBase = b * TT + qt * 128;
    const float scale = 0.08838834764831845f;   // 128^-0.5

    for (int i = 0; i < 16; i++) {
        int idx = tid + i * 256;
        int r = idx >> 5, d4 = idx & 31;
        int d = 4 * d4;
        float4 v = (d < 64)
            ? *reinterpret_cast<const float4*>(&g_q [(size_t)(rowBase + r) * 1024 + hh * 64 + d])
            : *reinterpret_cast<const float4*>(&g_qr[(size_t)(rowBase + r) * 1024 + hh * 64 + (d - 64)]);
        float4 s;
        s.x = __uint_as_float(f2tf(v.x * scale));
        s.y = __uint_as_float(f2tf(v.y * scale));
        s.z = __uint_as_float(f2tf(v.z * scale));
        s.w = __uint_as_float(f2tf(v.w * scale));
        *reinterpret_cast<float4*>(&S.Qs[r * QSTR + d]) = s;
    }

    const int rloc0 = warp * 16 + g;
    float m0 = -1e30f, m1 = -1e30f, l0 = 0.f, l1 = 0.f;
    float o[8][4];
#pragma unroll
    for (int nt = 0; nt < 8; nt++)
#pragma unroll
        for (int i = 0; i < 4; i++) o[nt][i] = 0.f;

    const int nkt = 2 * qt + 2;
    for (int j = 0; j < nkt; j++) {
        const int k0 = j * 64;
        __syncthreads();

#pragma unroll
        for (int i = 0; i < 8; i++) {
            int idx = tid + i * 256;
            int c = idx & 63, d4 = idx >> 6;
            int d = 4 * d4;
            int krow = b * TT + k0 + c;
            float4 v = (d < 64)
                ? *reinterpret_cast<const float4*>(&g_kv[(size_t)krow * 2048 + hh * 64 + d])
                : *reinterpret_cast<const float4*>(&g_kr[(size_t)krow * 64 + (d - 64)]);
            S.Ks[(d + 0) * KSTR + c] = __uint_as_float(f2tf(v.x));
            S.Ks[(d + 1) * KSTR + c] = __uint_as_float(f2tf(v.y));
            S.Ks[(d + 2) * KSTR + c] = __uint_as_float(f2tf(v.z));
            S.Ks[(d + 3) * KSTR + c] = __uint_as_float(f2tf(v.w));
        }
#pragma unroll
        for (int i = 0; i < 4; i++) {
            int idx = tid + i * 256;
            int r = idx >> 4, c4 = idx & 15;
            float4 v = *reinterpret_cast<const float4*>(
                &g_kv[(size_t)(b * TT + k0 + r) * 2048 + 1024 + hh * 64 + 4 * c4]);
            float4 s;
            s.x = __uint_as_float(f2tf(v.x));
            s.y = __uint_as_float(f2tf(v.y));
            s.z = __uint_as_float(f2tf(v.z));
            s.w = __uint_as_float(f2tf(v.w));
            *reinterpret_cast<float4*>(&S.Vs[r * KSTR + 4 * c4]) = s;
        }
        __syncthreads();

        float sc[8][4];
#pragma unroll
        for (int nt = 0; nt < 8; nt++)
#pragma unroll
            for (int i = 0; i < 4; i++) sc[nt][i] = 0.f;

#pragma unroll
        for (int ks = 0; ks < 16; ks++) {
            uint32_t a0 = __float_as_uint(S.Qs[(rloc0)     * QSTR + ks * 8 + t]);
            uint32_t a1 = __float_as_uint(S.Qs[(rloc0 + 8) * QSTR + ks * 8 + t]);
            uint32_t a2 = __float_as_uint(S.Qs[(rloc0)     * QSTR + ks * 8 + t + 4]);
            uint32_t a3 = __float_as_uint(S.Qs[(rloc0 + 8) * QSTR + ks * 8 + t + 4]);
#pragma unroll
            for (int nt = 0; nt < 8; nt++) {
                uint32_t b0 = __float_as_uint(S.Ks[(ks * 8 + t)     * KSTR + nt * 8 + g]);
                uint32_t b1 = __float_as_uint(S.Ks[(ks * 8 + t + 4) * KSTR + nt * 8 + g]);
                mma8(sc[nt], a0, a1, a2, a3, b0, b1);
            }
        }

        if (j >= 2 * qt) {
            int rg0 = qt * 128 + rloc0;
#pragma unroll
            for (int nt = 0; nt < 8; nt++) {
                int cg = k0 + nt * 8 + 2 * t;
                if (cg     > rg0)     sc[nt][0] = -1e30f;
                if (cg + 1 > rg0)     sc[nt][1] = -1e30f;
                if (cg     > rg0 + 8) sc[nt][2] = -1e30f;
                if (cg + 1 > rg0 + 8) sc[nt][3] = -1e30f;
            }
        }

        float mx0 = -1e30f, mx1 = -1e30f;
#pragma unroll
        for (int nt = 0; nt < 8; nt++) {
            mx0 = fmaxf(mx0, fmaxf(sc[nt][0], sc[nt][1]));
            mx1 = fmaxf(mx1, fmaxf(sc[nt][2], sc[nt][3]));
        }
        mx0 = fmaxf(mx0, __shfl_xor_sync(0xffffffffu, mx0, 1));
        mx0 = fmaxf(mx0, __shfl_xor_sync(0xffffffffu, mx0, 2));
        mx1 = fmaxf(mx1, __shfl_xor_sync(0xffffffffu, mx1, 1));
        mx1 = fmaxf(mx1, __shfl_xor_sync(0xffffffffu, mx1, 2));

        float mn0 = fmaxf(m0, mx0), mn1 = fmaxf(m1, mx1);
        float al0 = __expf(m0 - mn0), al1 = __expf(m1 - mn1);
        m0 = mn0; m1 = mn1;

        float sum0 = 0.f, sum1 = 0.f;
#pragma unroll
        for (int nt = 0; nt < 8; nt++) {
            float p0 = __expf(sc[nt][0] - mn0);
            float p1 = __expf(sc[nt][1] - mn0);
            float p2 = __expf(sc[nt][2] - mn1);
            float p3 = __expf(sc[nt][3] - mn1);
            sum0 += p0 + p1; sum1 += p2 + p3;
            float2 w0 = {__uint_as_float(f2tf(p0)), __uint_as_float(f2tf(p1))};
            float2 w1 = {__uint_as_float(f2tf(p2)), __uint_as_float(f2tf(p3))};
            *reinterpret_cast<float2*>(&S.Ps[(rloc0)     * KSTR + nt * 8 + 2 * t]) = w0;
            *reinterpret_cast<float2*>(&S.Ps[(rloc0 + 8) * KSTR + nt * 8 + 2 * t]) = w1;
        }
        sum0 += __shfl_xor_sync(0xffffffffu, sum0, 1);
        sum0 += __shfl_xor_sync(0xffffffffu, sum0, 2);
        sum1 += __shfl_xor_sync(0xffffffffu, sum1, 1);
        sum1 += __shfl_xor_sync(0xffffffffu, sum1, 2);
        l0 = l0 * al0 + sum0;
        l1 = l1 * al1 + sum1;

#pragma unroll
        for (int nt = 0; nt < 8; nt++) {
            o[nt][0] *= al0; o[nt][1] *= al0;
            o[nt][2] *= al1; o[nt][3] *= al1;
        }
        __syncwarp();

#pragma unroll
        for (int ks = 0; ks < 8; ks++) {
            uint32_t a0 = __float_as_uint(S.Ps[(rloc0)     * KSTR + ks * 8 + t]);
            uint32_t a1 = __float_as_uint(S.Ps[(rloc0 + 8) * KSTR + ks * 8 + t]);
            uint32_t a2 = __float_as_uint(S.Ps[(rloc0)     * KSTR + ks * 8 + t + 4]);
            uint32_t a3 = __float_as_uint(S.Ps[(rloc0 + 8) * KSTR + ks * 8 + t + 4]);
#pragma unroll
            for (int nt = 0; nt < 8; nt++) {
                uint32_t b0 = __float_as_uint(S.Vs[(ks * 8 + t)     * KSTR + nt * 8 + g]);
                uint32_t b1 = __float_as_uint(S.Vs[(ks * 8 + t + 4) * KSTR + nt * 8 + g]);
                mma8(o[nt], a0, a1, a2, a3, b0, b1);
            }
        }
    }

    float inv0 = 1.0f / l0, inv1 = 1.0f / l1;
    int rg = rowBase + rloc0;
#pragma unroll
    for (int nt = 0; nt < 8; nt++) {
        int col = hh * 64 + nt * 8 + 2 * t;
        float2 v0 = {o[nt][0] * inv0, o[nt][1] * inv0};
        float2 v1 = {o[nt][2] * inv1, o[nt][3] * inv1};
        *reinterpret_cast<float2*>(&g_att[(size_t)rg       * 1024 + col]) = v0;
        *reinterpret_cast<float2*>(&g_att[(size_t)(rg + 8) * 1024 + col]) = v1;
    }
}

// ---------------------------------------------------------------------------
// Launch
// ---------------------------------------------------------------------------
extern "C" void kernel_launch(void* const* d_in, const int* in_sizes, int n_in,
                              void* d_out, int out_size)
{
    (void)in_sizes; (void)n_in; (void)out_size;
    const float* x   = (const float*)d_in[0];
    const float* w1  = (const float*)d_in[1];
    const float* b1  = (const float*)d_in[2];
    const float* wkr = (const float*)d_in[3];
    const float* bkr = (const float*)d_in[4];
    const float* wqr = (const float*)d_in[5];
    const float* bqr = (const float*)d_in[6];
    const float* wkv = (const float*)d_in[7];
    const float* bkv = (const float*)d_in[8];
    const float* wq  = (const float*)d_in[9];
    const float* bq  = (const float*)d_in[10];
    const float* wo  = (const float*)d_in[11];
    const float* bo  = (const float*)d_in[12];
    float* out = (float*)d_out;

    float *h_, *kr_, *qr_, *kv_, *q_, *att_;
    cudaGetSymbolAddress((void**)&h_,   g_h);
    cudaGetSymbolAddress((void**)&kr_,  g_kr);
    cudaGetSymbolAddress((void**)&qr_,  g_qr);
    cudaGetSymbolAddress((void**)&kv_,  g_kv);
    cudaGetSymbolAddress((void**)&q_,   g_q);
    cudaGetSymbolAddress((void**)&att_, g_att);

    const int SM128 = (2 * 128 * 32 + 2 * 32 * 136) * 4;   // 67584
    const int SM64  = (2 * 128 * 32 + 2 * 32 * 72)  * 4;   // 51200
    const int SMAT  = (int)sizeof(AttnSm);
    cudaFuncSetAttribute(gemm_3x<128,128>, cudaFuncAttributeMaxDynamicSharedMemorySize, SM128);
    cudaFuncSetAttribute(gemm_3x<128,64>,  cudaFuncAttributeMaxDynamicSharedMemorySize, SM64);
    cudaFuncSetAttribute(attn_tc_kernel,   cudaFuncAttributeMaxDynamicSharedMemorySize, SMAT);

    // 1) h = x @ w1 + b1
    gemm_3x<128,128><<<dim3(8, 32), 256, SM128>>>(MR, 1024, 1024, x, 1024, w1, b1, h_);

    // 2) kr = rope(h @ wkr + bkr, 64)
    gemm_3x<128,64><<<dim3(1, 32), 256, SM64>>>(MR, 64, 1024, h_, 1024, wkr, bkr, kr_);
    rope_kernel<<<(MR * 32 + 255) / 256, 256>>>(kr_, 64);

    // 3) qr = rope(h @ wqr + bqr, 1024)
    gemm_3x<128,128><<<dim3(8, 32), 256, SM128>>>(MR, 1024, 1024, h_, 1024, wqr, bqr, qr_);
    rope_kernel<<<(MR * 512 + 255) / 256, 256>>>(qr_, 1024);

    // 4) kv = cKV @ wkv + bkv
    gemm_3x<128,128><<<dim3(16, 32), 256, SM128>>>(MR, 2048, 512, h_, 1024, wkv, bkv, kv_);

    // 5) q = cq @ wq + bq
    gemm_3x<128,128><<<dim3(8, 32), 256, SM128>>>(MR, 1024, 512, h_ + 512, 1024, wq, bq, q_);

    // 6) attention
    attn_tc_kernel<<<dim3(16, NH, BB), 256, SMAT>>>();

    // 7) out = att @ wo + bo
    gemm_3x<128,128><<<dim3(8, 32), 256, SM128>>>(MR, 1024, 1024, att_, 1024, wo, bo, out);
}

// round 6
// speedup vs baseline: 2.5690x; 1.0243x over previous
#include <cuda_runtime.h>
#include <cuda_bf16.h>
#include <math.h>
#include <stdint.h>

// Problem constants
#define BB   2
#define TT   2048
#define CC   1024
#define NH   16
#define LAT  512
#define DHR  64
#define MR   (BB*TT)        // 4096 rows

// ---------------------------------------------------------------------------
// Scratch (static device globals)
// ---------------------------------------------------------------------------
__device__ float g_kr [MR * 64];
__device__ float g_qr [MR * 1024];
__device__ float g_kv [MR * 2048];   // k cols 0..1023, v cols 1024..2047
__device__ float g_q  [MR * 1024];

// bf16 hi/lo split pairs (x ~= hi + lo; only hi*lo' terms dropped, ~2^-18)
__device__ __nv_bfloat16 g_xh[MR*1024],  g_xl[MR*1024];
__device__ __nv_bfloat16 g_hh[MR*1024],  g_hl[MR*1024];
__device__ __nv_bfloat16 g_ath[MR*1024], g_atl[MR*1024];
// transposed+split weights [N,K]
__device__ __nv_bfloat16 g_w1h [1024*1024], g_w1l [1024*1024];
__device__ __nv_bfloat16 g_wkrh[64*1024],   g_wkrl[64*1024];
__device__ __nv_bfloat16 g_wqrh[1024*1024], g_wqrl[1024*1024];
__device__ __nv_bfloat16 g_wkvh[2048*512],  g_wkvl[2048*512];
__device__ __nv_bfloat16 g_wqh [1024*512],  g_wql [1024*512];
__device__ __nv_bfloat16 g_woh [1024*1024], g_wol [1024*1024];

// ---------------------------------------------------------------------------
// helpers
// ---------------------------------------------------------------------------
__device__ __forceinline__ uint32_t f2tf(float f) {
    uint32_t u;
    asm("cvt.rna.tf32.f32 %0, %1;" : "=r"(u) : "f"(f));
    return u;
}
// tf32 m16n8k8 (attention)
__device__ __forceinline__ void mma8(float* c,
                                     uint32_t a0, uint32_t a1, uint32_t a2, uint32_t a3,
                                     uint32_t b0, uint32_t b1) {
    asm volatile(
        "mma.sync.aligned.m16n8k8.row.col.f32.tf32.tf32.f32 "
        "{%0,%1,%2,%3},{%4,%5,%6,%7},{%8,%9},{%0,%1,%2,%3};"
        : "+f"(c[0]), "+f"(c[1]), "+f"(c[2]), "+f"(c[3])
        : "r"(a0), "r"(a1), "r"(a2), "r"(a3), "r"(b0), "r"(b1));
}
// bf16 m16n8k16
__device__ __forceinline__ void mma16(float* c, const uint32_t* a,
                                      uint32_t b0, uint32_t b1) {
    asm volatile(
        "mma.sync.aligned.m16n8k16.row.col.f32.bf16.bf16.f32 "
        "{%0,%1,%2,%3},{%4,%5,%6,%7},{%8,%9},{%0,%1,%2,%3};"
        : "+f"(c[0]), "+f"(c[1]), "+f"(c[2]), "+f"(c[3])
        : "r"(a[0]), "r"(a[1]), "r"(a[2]), "r"(a[3]), "r"(b0), "r"(b1));
}
// Dekker bf16 split of a pair: hi = bf16x2(x low half, y high), lo = residuals
__device__ __forceinline__ void split2(float x, float y, uint32_t& hi, uint32_t& lo) {
    uint32_t h, l;
    asm("cvt.rn.bf16x2.f32 %0, %1, %2;" : "=r"(h) : "f"(y), "f"(x));
    float hx = __uint_as_float(h << 16);
    float hy = __uint_as_float(h & 0xffff0000u);
    float lx = x - hx;
    float ly = y - hy;
    asm("cvt.rn.bf16x2.f32 %0, %1, %2;" : "=r"(l) : "f"(ly), "f"(lx));
    hi = h; lo = l;
}
__device__ __forceinline__ uint32_t sptr(const void* p) {
    return (uint32_t)__cvta_generic_to_shared(p);
}
__device__ __forceinline__ void cp16(uint32_t dst, const void* src) {
    asm volatile("cp.async.cg.shared.global [%0], [%1], 16;" :: "r"(dst), "l"(src));
}
__device__ __forceinline__ void cp_commit() {
    asm volatile("cp.async.commit_group;");
}
template<int N> __device__ __forceinline__ void cp_wait() {
    asm volatile("cp.async.wait_group %0;" :: "n"(N));
}

// ---------------------------------------------------------------------------
// Weight transpose + split: W[K,N] fp32 -> Wh,Wl[N,K] bf16
// ---------------------------------------------------------------------------
__global__ void wsplit_kernel(const float* __restrict__ W, int K, int N,
                              __nv_bfloat16* __restrict__ Wh,
                              __nv_bfloat16* __restrict__ Wl)
{
    __shared__ float tile[32][33];
    int n0 = blockIdx.x * 32, k0 = blockIdx.y * 32;
    int tx = threadIdx.x, ty = threadIdx.y;
#pragma unroll
    for (int i = 0; i < 32; i += 8)
        tile[ty + i][tx] = W[(size_t)(k0 + ty + i) * N + n0 + tx];
    __syncthreads();
#pragma unroll
    for (int i = 0; i < 32; i += 8) {
        int n = n0 + ty + i, k = k0 + tx;
        float v = tile[tx][ty + i];
        __nv_bfloat16 h = __float2bfloat16(v);
        float lo = v - __bfloat162float(h);
        Wh[(size_t)n * K + k] = h;
        Wl[(size_t)n * K + k] = __float2bfloat16(lo);
    }
}

// x split (no transpose), float4 granularity
__global__ void asplit_kernel(const float4* __restrict__ X,
                              uint2* __restrict__ Xh, uint2* __restrict__ Xl, int n4)
{
    int i = blockIdx.x * blockDim.x + threadIdx.x;
    if (i >= n4) return;
    float4 v = X[i];
    uint32_t h0, l0, h1, l1;
    split2(v.x, v.y, h0, l0);
    split2(v.z, v.w, h1, l1);
    Xh[i] = make_uint2(h0, h1);
    Xl[i] = make_uint2(l0, l1);
}

// ---------------------------------------------------------------------------
// Split-bf16 3-pass mma.sync GEMM, pre-split operands.
// C[M,N] = (Ah+Al)[M,K] @ (Bh+Bl)[N,K]^T + bias   (3 cross terms)
// A: bf16 hi/lo [M,K] row-major (lda). B: bf16 hi/lo [N,K] (K contiguous).
// BM=128, BK=32, 8 warps (4x2). Smem rows padded to 40 bf16 (80B) ->
// fragment LDS.32 reads are bank-conflict-free.
// ---------------------------------------------------------------------------
template<int BN, bool SPLIT_OUT>
__global__ __launch_bounds__(256, 2)
void gemm_bf16_3x(int N, int K,
                  const __nv_bfloat16* __restrict__ Agh,
                  const __nv_bfloat16* __restrict__ Agl, int lda,
                  const __nv_bfloat16* __restrict__ Bgh,
                  const __nv_bfloat16* __restrict__ Bgl,
                  const float* __restrict__ bias,
                  float* __restrict__ C,
                  __nv_bfloat16* __restrict__ Ch,
                  __nv_bfloat16* __restrict__ Cl)
{
    constexpr int BM   = 128;
    constexpr int WM   = BM / 4;          // 32
    constexpr int WN   = BN / 2;
    constexpr int MT   = WM / 16;         // 2
    constexpr int NT   = WN / 8;
    constexpr int STR  = 40;              // padded row stride (bf16 elems)
    constexpr int ASL  = BM * STR;        // elems per A slab
    constexpr int BSL  = BN * STR;
    constexpr int STG  = 2 * ASL + 2 * BSL;   // elems per stage
    constexpr int NAC  = (BM * 4) / 256;      // 16B chunks per thread (A hi)
    constexpr int NBC  = (BN * 4) / 256;

    extern __shared__ __nv_bfloat16 smb[];

    const int tid  = threadIdx.x;
    const int lane = tid & 31;
    const int warp = tid >> 5;
    const int g    = lane >> 2;
    const int t    = lane & 3;
    const int wm   = warp >> 1;
    const int wn   = warp & 1;
    const int bRow = blockIdx.y * BM;
    const int bCol = blockIdx.x * BN;

    float acc[MT][NT][4];
#pragma unroll
    for (int mt = 0; mt < MT; mt++)
#pragma unroll
        for (int nt = 0; nt < NT; nt++)
#pragma unroll
            for (int i = 0; i < 4; i++) acc[mt][nt][i] = 0.f;

    auto issue = [&](int k0, int s) {
        __nv_bfloat16* st = smb + s * STG;
#pragma unroll
        for (int i = 0; i < NAC; i++) {
            int idx = tid + i * 256;
            int r = idx >> 2, c = idx & 3;       // 4 x 16B chunks per 64B row
            uint32_t d = sptr(st + r * STR + c * 8);
            const __nv_bfloat16* sh = Agh + (size_t)(bRow + r) * lda + k0 + c * 8;
            const __nv_bfloat16* sl = Agl + (size_t)(bRow + r) * lda + k0 + c * 8;
            cp16(d, sh);
            cp16(d + ASL * 2, sl);               // byte offset
        }
#pragma unroll
        for (int i = 0; i < NBC; i++) {
            int idx = tid + i * 256;
            int r = idx >> 2, c = idx & 3;
            uint32_t d = sptr(st + 2 * ASL + r * STR + c * 8);
            const __nv_bfloat16* sh = Bgh + (size_t)(bCol + r) * K + k0 + c * 8;
            const __nv_bfloat16* sl = Bgl + (size_t)(bCol + r) * K + k0 + c * 8;
            cp16(d, sh);
            cp16(d + BSL * 2, sl);
        }
        cp_commit();
    };

    const int iters = K / 32;
    issue(0, 0);

    for (int it = 0; it < iters; it++) {
        const int cur = it & 1;
        if (it + 1 < iters) { issue((it + 1) * 32, cur ^ 1); cp_wait<1>(); }
        else                { cp_wait<0>(); }
        __syncthreads();

        const __nv_bfloat16* Ah = smb + cur * STG;
        const __nv_bfloat16* Al = Ah + ASL;
        const __nv_bfloat16* Bh = Ah + 2 * ASL;
        const __nv_bfloat16* Bl = Bh + BSL;

#pragma unroll
        for (int s = 0; s < 2; s++) {
            const int kb = 16 * s + 2 * t;       // even element index
            uint32_t ah[MT][4], al[MT][4];
#pragma unroll
            for (int mt = 0; mt < MT; mt++) {
                int r0 = wm * WM + mt * 16 + g;
                int r1 = r0 + 8;
                ah[mt][0] = *reinterpret_cast<const uint32_t*>(&Ah[r0 * STR + kb]);
                ah[mt][1] = *reinterpret_cast<const uint32_t*>(&Ah[r1 * STR + kb]);
                ah[mt][2] = *reinterpret_cast<const uint32_t*>(&Ah[r0 * STR + kb + 8]);
                ah[mt][3] = *reinterpret_cast<const uint32_t*>(&Ah[r1 * STR + kb + 8]);
                al[mt][0] = *reinterpret_cast<const uint32_t*>(&Al[r0 * STR + kb]);
                al[mt][1] = *reinterpret_cast<const uint32_t*>(&Al[r1 * STR + kb]);
                al[mt][2] = *reinterpret_cast<const uint32_t*>(&Al[r0 * STR + kb + 8]);
                al[mt][3] = *reinterpret_cast<const uint32_t*>(&Al[r1 * STR + kb + 8]);
            }
#pragma unroll
            for (int nt = 0; nt < NT; nt++) {
                int nb = wn * WN + nt * 8 + g;
                uint32_t bh0 = *reinterpret_cast<const uint32_t*>(&Bh[nb * STR + kb]);
                uint32_t bh1 = *reinterpret_cast<const uint32_t*>(&Bh[nb * STR + kb + 8]);
                uint32_t bl0 = *reinterpret_cast<const uint32_t*>(&Bl[nb * STR + kb]);
                uint32_t bl1 = *reinterpret_cast<const uint32_t*>(&Bl[nb * STR + kb + 8]);
#pragma unroll
                for (int mt = 0; mt < MT; mt++) {
                    mma16(acc[mt][nt], ah[mt], bh0, bh1);
                    mma16(acc[mt][nt], ah[mt], bl0, bl1);
                    mma16(acc[mt][nt], al[mt], bh0, bh1);
                }
            }
        }
        __syncthreads();
    }

#pragma unroll
    for (int mt = 0; mt < MT; mt++) {
        int r0 = bRow + wm * WM + mt * 16 + g;
#pragma unroll
        for (int nt = 0; nt < NT; nt++) {
            int col = bCol + wn * WN + nt * 8 + 2 * t;
            float bx = bias[col], by = bias[col + 1];
            float v00 = acc[mt][nt][0] + bx, v01 = acc[mt][nt][1] + by;
            float v10 = acc[mt][nt][2] + bx, v11 = acc[mt][nt][3] + by;
            if (!SPLIT_OUT) {
                float2 a = {v00, v01}, b = {v10, v11};
                *reinterpret_cast<float2*>(C + (size_t)r0 * N + col)       = a;
                *reinterpret_cast<float2*>(C + (size_t)(r0 + 8) * N + col) = b;
            } else {
                uint32_t h0, l0, h1, l1;
                split2(v00, v01, h0, l0);
                split2(v10, v11, h1, l1);
                *reinterpret_cast<uint32_t*>(&Ch[(size_t)r0 * N + col])       = h0;
                *reinterpret_cast<uint32_t*>(&Cl[(size_t)r0 * N + col])       = l0;
                *reinterpret_cast<uint32_t*>(&Ch[(size_t)(r0 + 8) * N + col]) = h1;
                *reinterpret_cast<uint32_t*>(&Cl[(size_t)(r0 + 8) * N + col]) = l1;
            }
        }
    }
}

// ---------------------------------------------------------------------------
// RoPE (unchanged)
// ---------------------------------------------------------------------------
__global__ void rope_kernel(float* __restrict__ x, int D)
{
    const int pairs = D / 2;
    int idx = blockIdx.x * blockDim.x + threadIdx.x;
    if (idx >= MR * pairs) return;
    int row = idx / pairs;
    int i   = idx - row * pairs;
    int t   = row & (TT - 1);

    float theta = expf(-2.0f * (float)i / (float)D * 9.2103403719761836f);
    float ang   = (float)(t + 1) * theta;
    float sn, cs;
    sincosf(ang, &sn, &cs);

    float* p = x + (size_t)row * D + 2*i;
    float e = p[0], o = p[1];
    p[0] = e * cs - o * sn;
    p[1] = o * cs + e * sn;
}

// ---------------------------------------------------------------------------
// Tensor-core causal flash attention (tf32 mma.sync). dqk=128, dv=64.
// Epilogue writes split bf16 (att feeds only the wo GEMM).
// ---------------------------------------------------------------------------
#define QSTR 136
#define KSTR 72

struct AttnSm {
    float Qs[128 * QSTR];
    float Ks[128 * KSTR];
    float Vs[64 * KSTR];
    float Ps[128 * KSTR];
};

__global__ __launch_bounds__(256, 1)
void attn_tc_kernel()
{
    extern __shared__ char smraw[];
    AttnSm& S = *reinterpret_cast<AttnSm*>(smraw);

    const int tid  = threadIdx.x;
    const int lane = tid & 31;
    const int warp = tid >> 5;
    const int g    = lane >> 2;
    const int t    = lane & 3;
    const int qt   = blockIdx.x;
    const int hh   = blockIdx.y;
    const int b    = blockIdx.z;
    const int rowBase = b * TT + qt * 128;
    const float scale = 0.08838834764831845f;   // 128^-0.5

    for (int i = 0; i < 16; i++) {
        int idx = tid + i * 256;
        int r = idx >> 5, d4 = idx & 31;
        int d = 4 * d4;
        float4 v = (d < 64)
            ? *reinterpret_cast<const float4*>(&g_q [(size_t)(rowBase + r) * 1024 + hh * 64 + d])
            : *reinterpret_cast<const float4*>(&g_qr[(size_t)(rowBase + r) * 1024 + hh * 64 + (d - 64)]);
        float4 s;
        s.x = __uint_as_float(f2tf(v.x * scale));
        s.y = __uint_as_float(f2tf(v.y * scale));
        s.z = __uint_as_float(f2tf(v.z * scale));
        s.w = __uint_as_float(f2tf(v.w * scale));
        *reinterpret_cast<float4*>(&S.Qs[r * QSTR + d]) = s;
    }

    const int rloc0 = warp * 16 + g;
    float m0 = -1e30f, m1 = -1e30f, l0 = 0.f, l1 = 0.f;
    float o[8][4];
#pragma unroll
    for (int nt = 0; nt < 8; nt++)
#pragma unroll
        for (int i = 0; i < 4; i++) o[nt][i] = 0.f;

    const int nkt = 2 * qt + 2;
    for (int j = 0; j < nkt; j++) {
        const int k0 = j * 64;
        __syncthreads();

#pragma unroll
        for (int i = 0; i < 8; i++) {
            int idx = tid + i * 256;
            int c = idx & 63, d4 = idx >> 6;
            int d = 4 * d4;
            int krow = b * TT + k0 + c;
            float4 v = (d < 64)
                ? *reinterpret_cast<const float4*>(&g_kv[(size_t)krow * 2048 + hh * 64 + d])
                : *reinterpret_cast<const float4*>(&g_kr[(size_t)krow * 64 + (d - 64)]);
            S.Ks[(d + 0) * KSTR + c] = __uint_as_float(f2tf(v.x));
            S.Ks[(d + 1) * KSTR + c] = __uint_as_float(f2tf(v.y));
            S.Ks[(d + 2) * KSTR + c] = __uint_as_float(f2tf(v.z));
            S.Ks[(d + 3) * KSTR + c] = __uint_as_float(f2tf(v.w));
        }
#pragma unroll
        for (int i = 0; i < 4; i++) {
            int idx = tid + i * 256;
            int r = idx >> 4, c4 = idx & 15;
            float4 v = *reinterpret_cast<const float4*>(
                &g_kv[(size_t)(b * TT + k0 + r) * 2048 + 1024 + hh * 64 + 4 * c4]);
            float4 s;
            s.x = __uint_as_float(f2tf(v.x));
            s.y = __uint_as_float(f2tf(v.y));
            s.z = __uint_as_float(f2tf(v.z));
            s.w = __uint_as_float(f2tf(v.w));
            *reinterpret_cast<float4*>(&S.Vs[r * KSTR + 4 * c4]) = s;
        }
        __syncthreads();

        float sc[8][4];
#pragma unroll
        for (int nt = 0; nt < 8; nt++)
#pragma unroll
            for (int i = 0; i < 4; i++) sc[nt][i] = 0.f;

#pragma unroll
        for (int ks = 0; ks < 16; ks++) {
            uint32_t a0 = __float_as_uint(S.Qs[(rloc0)     * QSTR + ks * 8 + t]);
            uint32_t a1 = __float_as_uint(S.Qs[(rloc0 + 8) * QSTR + ks * 8 + t]);
            uint32_t a2 = __float_as_uint(S.Qs[(rloc0)     * QSTR + ks * 8 + t + 4]);
            uint32_t a3 = __float_as_uint(S.Qs[(rloc0 + 8) * QSTR + ks * 8 + t + 4]);
#pragma unroll
            for (int nt = 0; nt < 8; nt++) {
                uint32_t b0 = __float_as_uint(S.Ks[(ks * 8 + t)     * KSTR + nt * 8 + g]);
                uint32_t b1 = __float_as_uint(S.Ks[(ks * 8 + t + 4) * KSTR + nt * 8 + g]);
                mma8(sc[nt], a0, a1, a2, a3, b0, b1);
            }
        }

        if (j >= 2 * qt) {
            int rg0 = qt * 128 + rloc0;
#pragma unroll
            for (int nt = 0; nt < 8; nt++) {
                int cg = k0 + nt * 8 + 2 * t;
                if (cg     > rg0)     sc[nt][0] = -1e30f;
                if (cg + 1 > rg0)     sc[nt][1] = -1e30f;
                if (cg     > rg0 + 8) sc[nt][2] = -1e30f;
                if (cg + 1 > rg0 + 8) sc[nt][3] = -1e30f;
            }
        }

        float mx0 = -1e30f, mx1 = -1e30f;
#pragma unroll
        for (int nt = 0; nt < 8; nt++) {
            mx0 = fmaxf(mx0, fmaxf(sc[nt][0], sc[nt][1]));
            mx1 = fmaxf(mx1, fmaxf(sc[nt][2], sc[nt][3]));
        }
        mx0 = fmaxf(mx0, __shfl_xor_sync(0xffffffffu, mx0, 1));
        mx0 = fmaxf(mx0, __shfl_xor_sync(0xffffffffu, mx0, 2));
        mx1 = fmaxf(mx1, __shfl_xor_sync(0xffffffffu, mx1, 1));
        mx1 = fmaxf(mx1, __shfl_xor_sync(0xffffffffu, mx1, 2));

        float mn0 = fmaxf(m0, mx0), mn1 = fmaxf(m1, mx1);
        float al0 = __expf(m0 - mn0), al1 = __expf(m1 - mn1);
        m0 = mn0; m1 = mn1;

        float sum0 = 0.f, sum1 = 0.f;
#pragma unroll
        for (int nt = 0; nt < 8; nt++) {
            float p0 = __expf(sc[nt][0] - mn0);
            float p1 = __expf(sc[nt][1] - mn0);
            float p2 = __expf(sc[nt][2] - mn1);
            float p3 = __expf(sc[nt][3] - mn1);
            sum0 += p0 + p1; sum1 += p2 + p3;
            float2 w0 = {__uint_as_float(f2tf(p0)), __uint_as_float(f2tf(p1))};
            float2 w1 = {__uint_as_float(f2tf(p2)), __uint_as_float(f2tf(p3))};
            *reinterpret_cast<float2*>(&S.Ps[(rloc0)     * KSTR + nt * 8 + 2 * t]) = w0;
            *reinterpret_cast<float2*>(&S.Ps[(rloc0 + 8) * KSTR + nt * 8 + 2 * t]) = w1;
        }
        sum0 += __shfl_xor_sync(0xffffffffu, sum0, 1);
        sum0 += __shfl_xor_sync(0xffffffffu, sum0, 2);
        sum1 += __shfl_xor_sync(0xffffffffu, sum1, 1);
        sum1 += __shfl_xor_sync(0xffffffffu, sum1, 2);
        l0 = l0 * al0 + sum0;
        l1 = l1 * al1 + sum1;

#pragma unroll
        for (int nt = 0; nt < 8; nt++) {
            o[nt][0] *= al0; o[nt][1] *= al0;
            o[nt][2] *= al1; o[nt][3] *= al1;
        }
        __syncwarp();

#pragma unroll
        for (int ks = 0; ks < 8; ks++) {
            uint32_t a0 = __float_as_uint(S.Ps[(rloc0)     * KSTR + ks * 8 + t]);
            uint32_t a1 = __float_as_uint(S.Ps[(rloc0 + 8) * KSTR + ks * 8 + t]);
            uint32_t a2 = __float_as_uint(S.Ps[(rloc0)     * KSTR + ks * 8 + t + 4]);
            uint32_t a3 = __float_as_uint(S.Ps[(rloc0 + 8) * KSTR + ks * 8 + t + 4]);
#pragma unroll
            for (int nt = 0; nt < 8; nt++) {
                uint32_t b0 = __float_as_uint(S.Vs[(ks * 8 + t)     * KSTR + nt * 8 + g]);
                uint32_t b1 = __float_as_uint(S.Vs[(ks * 8 + t + 4) * KSTR + nt * 8 + g]);
                mma8(o[nt], a0, a1, a2, a3, b0, b1);
            }
        }
    }

    // finalize + store split bf16 (att feeds only the wo GEMM)
    float inv0 = 1.0f / l0, inv1 = 1.0f / l1;
    int rg = rowBase + rloc0;
#pragma unroll
    for (int nt = 0; nt < 8; nt++) {
        int col = hh * 64 + nt * 8 + 2 * t;
        uint32_t h0, l0u, h1, l1u;
        split2(o[nt][0] * inv0, o[nt][1] * inv0, h0, l0u);
        split2(o[nt][2] * inv1, o[nt][3] * inv1, h1, l1u);
        *reinterpret_cast<uint32_t*>(&g_ath[(size_t)rg       * 1024 + col]) = h0;
        *reinterpret_cast<uint32_t*>(&g_atl[(size_t)rg       * 1024 + col]) = l0u;
        *reinterpret_cast<uint32_t*>(&g_ath[(size_t)(rg + 8) * 1024 + col]) = h1;
        *reinterpret_cast<uint32_t*>(&g_atl[(size_t)(rg + 8) * 1024 + col]) = l1u;
    }
}

// ---------------------------------------------------------------------------
// Launch
// ---------------------------------------------------------------------------
extern "C" void kernel_launch(void* const* d_in, const int* in_sizes, int n_in,
                              void* d_out, int out_size)
{
    (void)in_sizes; (void)n_in; (void)out_size;
    const float* x   = (const float*)d_in[0];
    const float* w1  = (const float*)d_in[1];
    const float* b1  = (const float*)d_in[2];
    const float* wkr = (const float*)d_in[3];
    const float* bkr = (const float*)d_in[4];
    const float* wqr = (const float*)d_in[5];
    const float* bqr = (const float*)d_in[6];
    const float* wkv = (const float*)d_in[7];
    const float* bkv = (const float*)d_in[8];
    const float* wq  = (const float*)d_in[9];
    const float* bq  = (const float*)d_in[10];
    const float* wo  = (const float*)d_in[11];
    const float* bo  = (const float*)d_in[12];
    float* out = (float*)d_out;

    float *kr_, *qr_, *kv_, *q_;
    __nv_bfloat16 *xh_, *xl_, *hh_, *hl_, *ath_, *atl_;
    __nv_bfloat16 *w1h_, *w1l_, *wkrh_, *wkrl_, *wqrh_, *wqrl_;
    __nv_bfloat16 *wkvh_, *wkvl_, *wqh_, *wql_, *woh_, *wol_;
    cudaGetSymbolAddress((void**)&kr_,  g_kr);
    cudaGetSymbolAddress((void**)&qr_,  g_qr);
    cudaGetSymbolAddress((void**)&kv_,  g_kv);
    cudaGetSymbolAddress((void**)&q_,   g_q);
    cudaGetSymbolAddress((void**)&xh_,  g_xh);  cudaGetSymbolAddress((void**)&xl_,  g_xl);
    cudaGetSymbolAddress((void**)&hh_,  g_hh);  cudaGetSymbolAddress((void**)&hl_,  g_hl);
    cudaGetSymbolAddress((void**)&ath_, g_ath); cudaGetSymbolAddress((void**)&atl_, g_atl);
    cudaGetSymbolAddress((void**)&w1h_, g_w1h);  cudaGetSymbolAddress((void**)&w1l_, g_w1l);
    cudaGetSymbolAddress((void**)&wkrh_, g_wkrh); cudaGetSymbolAddress((void**)&wkrl_, g_wkrl);
    cudaGetSymbolAddress((void**)&wqrh_, g_wqrh); cudaGetSymbolAddress((void**)&wqrl_, g_wqrl);
    cudaGetSymbolAddress((void**)&wkvh_, g_wkvh); cudaGetSymbolAddress((void**)&wkvl_, g_wkvl);
    cudaGetSymbolAddress((void**)&wqh_, g_wqh);   cudaGetSymbolAddress((void**)&wql_, g_wql);
    cudaGetSymbolAddress((void**)&woh_, g_woh);   cudaGetSymbolAddress((void**)&wol_, g_wol);

    // smem sizes: 2 stages * (2*A + 2*B) slabs of (rows*40 bf16)
    const int SMG128 = 2 * (2 * 128 * 40 + 2 * 128 * 40) * 2;   // 81920
    const int SMG64  = 2 * (2 * 128 * 40 + 2 * 64  * 40) * 2;   // 61440
    const int SMAT   = (int)sizeof(AttnSm);
    cudaFuncSetAttribute(gemm_bf16_3x<128, false>, cudaFuncAttributeMaxDynamicSharedMemorySize, SMG128);
    cudaFuncSetAttribute(gemm_bf16_3x<128, true>,  cudaFuncAttributeMaxDynamicSharedMemorySize, SMG128);
    cudaFuncSetAttribute(gemm_bf16_3x<64,  false>, cudaFuncAttributeMaxDynamicSharedMemorySize, SMG64);
    cudaFuncSetAttribute(attn_tc_kernel,           cudaFuncAttributeMaxDynamicSharedMemorySize, SMAT);

    dim3 wsb(32, 8);
    // weight transforms
    wsplit_kernel<<<dim3(1024/32, 1024/32), wsb>>>(w1,  1024, 1024, w1h_,  w1l_);
    wsplit_kernel<<<dim3(64/32,   1024/32), wsb>>>(wkr, 1024, 64,   wkrh_, wkrl_);
    wsplit_kernel<<<dim3(1024/32, 1024/32), wsb>>>(wqr, 1024, 1024, wqrh_, wqrl_);
    wsplit_kernel<<<dim3(2048/32, 512/32),  wsb>>>(wkv, 512,  2048, wkvh_, wkvl_);
    wsplit_kernel<<<dim3(1024/32, 512/32),  wsb>>>(wq,  512,  1024, wqh_,  wql_);
    wsplit_kernel<<<dim3(1024/32, 1024/32), wsb>>>(wo,  1024, 1024, woh_,  wol_);
    // x split
    asplit_kernel<<<(MR * 1024 / 4 + 255) / 256, 256>>>(
        (const float4*)x, (uint2*)xh_, (uint2*)xl_, MR * 1024 / 4);

    // 1) h = x @ w1 + b1  -> split bf16 h
    gemm_bf16_3x<128, true><<<dim3(8, 32), 256, SMG128>>>(
        1024, 1024, xh_, xl_, 1024, w1h_, w1l_, b1, nullptr, hh_, hl_);

    // 2) kr = rope(h @ wkr + bkr)
    gemm_bf16_3x<64, false><<<dim3(1, 32), 256, SMG64>>>(
        64, 1024, hh_, hl_, 1024, wkrh_, wkrl_, bkr, kr_, nullptr, nullptr);
    rope_kernel<<<(MR * 32 + 255) / 256, 256>>>(kr_, 64);

    // 3) qr = rope(h @ wqr + bqr)
    gemm_bf16_3x<128, false><<<dim3(8, 32), 256, SMG128>>>(
        1024, 1024, hh_, hl_, 1024, wqrh_, wqrl_, bqr, qr_, nullptr, nullptr);
    rope_kernel<<<(MR * 512 + 255) / 256, 256>>>(qr_, 1024);

    // 4) kv = cKV @ wkv + bkv   (cKV = h cols 0..511)
    gemm_bf16_3x<128, false><<<dim3(16, 32), 256, SMG128>>>(
        2048, 512, hh_, hl_, 1024, wkvh_, wkvl_, bkv, kv_, nullptr, nullptr);

    // 5) q = cq @ wq + bq       (cq = h cols 512..1023)
    gemm_bf16_3x<128, false><<<dim3(8, 32), 256, SMG128>>>(
        1024, 512, hh_ + 512, hl_ + 512, 1024, wqh_, wql_, bq, q_, nullptr, nullptr);

    // 6) attention -> split bf16 att
    attn_tc_kernel<<<dim3(16, NH, BB), 256, SMAT>>>();

    // 7) out = att @ wo + bo
    gemm_bf16_3x<128, false><<<dim3(8, 32), 256, SMG128>>>(
        1024, 1024, ath_, atl_, 1024, woh_, wol_, bo, out, nullptr, nullptr);
}

// round 7
// speedup vs baseline: 2.9687x; 1.1556x over previous
#include <cuda_runtime.h>
#include <cuda_bf16.h>
#include <math.h>
#include <stdint.h>

// Problem constants
#define BB   2
#define TT   2048
#define CC   1024
#define NH   16
#define LAT  512
#define DHR  64
#define MR   (BB*TT)        // 4096 rows

// ---------------------------------------------------------------------------
// Scratch (static device globals)
// ---------------------------------------------------------------------------
__device__ float g_kr [MR * 64];
__device__ float g_qr [MR * 1024];
__device__ float g_kv [MR * 2048];   // k cols 0..1023, v cols 1024..2047
__device__ float g_q  [MR * 1024];

// bf16 hi/lo split pairs (x ~= hi + lo)
__device__ __nv_bfloat16 g_xh[MR*1024],  g_xl[MR*1024];
__device__ __nv_bfloat16 g_hh[MR*1024],  g_hl[MR*1024];
__device__ __nv_bfloat16 g_ath[MR*1024], g_atl[MR*1024];
// transposed+split weights [N,K]
__device__ __nv_bfloat16 g_w1h [1024*1024], g_w1l [1024*1024];
__device__ __nv_bfloat16 g_wkrh[64*1024],   g_wkrl[64*1024];
__device__ __nv_bfloat16 g_wqrh[1024*1024], g_wqrl[1024*1024];
__device__ __nv_bfloat16 g_wkvh[2048*512],  g_wkvl[2048*512];
__device__ __nv_bfloat16 g_wqh [1024*512],  g_wql [1024*512];
__device__ __nv_bfloat16 g_woh [1024*1024], g_wol [1024*1024];

// ---------------------------------------------------------------------------
// helpers
// ---------------------------------------------------------------------------
__device__ __forceinline__ uint32_t f2tf(float f) {
    uint32_t u;
    asm("cvt.rna.tf32.f32 %0, %1;" : "=r"(u) : "f"(f));
    return u;
}
__device__ __forceinline__ void mma8(float* c,
                                     uint32_t a0, uint32_t a1, uint32_t a2, uint32_t a3,
                                     uint32_t b0, uint32_t b1) {
    asm volatile(
        "mma.sync.aligned.m16n8k8.row.col.f32.tf32.tf32.f32 "
        "{%0,%1,%2,%3},{%4,%5,%6,%7},{%8,%9},{%0,%1,%2,%3};"
        : "+f"(c[0]), "+f"(c[1]), "+f"(c[2]), "+f"(c[3])
        : "r"(a0), "r"(a1), "r"(a2), "r"(a3), "r"(b0), "r"(b1));
}
__device__ __forceinline__ void mma16(float* c, const uint32_t* a,
                                      uint32_t b0, uint32_t b1) {
    asm volatile(
        "mma.sync.aligned.m16n8k16.row.col.f32.bf16.bf16.f32 "
        "{%0,%1,%2,%3},{%4,%5,%6,%7},{%8,%9},{%0,%1,%2,%3};"
        : "+f"(c[0]), "+f"(c[1]), "+f"(c[2]), "+f"(c[3])
        : "r"(a[0]), "r"(a[1]), "r"(a[2]), "r"(a[3]), "r"(b0), "r"(b1));
}
__device__ __forceinline__ void split2(float x, float y, uint32_t& hi, uint32_t& lo) {
    uint32_t h, l;
    asm("cvt.rn.bf16x2.f32 %0, %1, %2;" : "=r"(h) : "f"(y), "f"(x));
    float hx = __uint_as_float(h << 16);
    float hy = __uint_as_float(h & 0xffff0000u);
    float lx = x - hx;
    float ly = y - hy;
    asm("cvt.rn.bf16x2.f32 %0, %1, %2;" : "=r"(l) : "f"(ly), "f"(lx));
    hi = h; lo = l;
}
__device__ __forceinline__ uint32_t sptr(const void* p) {
    return (uint32_t)__cvta_generic_to_shared(p);
}
__device__ __forceinline__ void cp16(uint32_t dst, const void* src) {
    asm volatile("cp.async.cg.shared.global [%0], [%1], 16;" :: "r"(dst), "l"(src));
}
__device__ __forceinline__ void cp_commit() {
    asm volatile("cp.async.commit_group;");
}
template<int N> __device__ __forceinline__ void cp_wait() {
    asm volatile("cp.async.wait_group %0;" :: "n"(N));
}

// ---------------------------------------------------------------------------
// Weight transpose + split: W[K,N] fp32 -> Wh,Wl[N,K] bf16
// ---------------------------------------------------------------------------
__global__ void wsplit_kernel(const float* __restrict__ W, int K, int N,
                              __nv_bfloat16* __restrict__ Wh,
                              __nv_bfloat16* __restrict__ Wl)
{
    __shared__ float tile[32][33];
    int n0 = blockIdx.x * 32, k0 = blockIdx.y * 32;
    int tx = threadIdx.x, ty = threadIdx.y;
#pragma unroll
    for (int i = 0; i < 32; i += 8)
        tile[ty + i][tx] = W[(size_t)(k0 + ty + i) * N + n0 + tx];
    __syncthreads();
#pragma unroll
    for (int i = 0; i < 32; i += 8) {
        int n = n0 + ty + i, k = k0 + tx;
        float v = tile[tx][ty + i];
        __nv_bfloat16 h = __float2bfloat16(v);
        float lo = v - __bfloat162float(h);
        Wh[(size_t)n * K + k] = h;
        Wl[(size_t)n * K + k] = __float2bfloat16(lo);
    }
}

__global__ void asplit_kernel(const float4* __restrict__ X,
                              uint2* __restrict__ Xh, uint2* __restrict__ Xl, int n4)
{
    int i = blockIdx.x * blockDim.x + threadIdx.x;
    if (i >= n4) return;
    float4 v = X[i];
    uint32_t h0, l0, h1, l1;
    split2(v.x, v.y, h0, l0);
    split2(v.z, v.w, h1, l1);
    Xh[i] = make_uint2(h0, h1);
    Xl[i] = make_uint2(l0, l1);
}

// ---------------------------------------------------------------------------
// Split-bf16 3-pass mma.sync GEMM, pre-split operands.
// TF32O: round output to tf32 grid (consumed raw by attention).
// oscale: output scaling (folds softmax 1/sqrt(dk) into q/qr projections).
// ---------------------------------------------------------------------------
template<int BN, bool SPLIT_OUT, bool TF32O>
__global__ __launch_bounds__(256, 2)
void gemm_bf16_3x(int N, int K,
                  const __nv_bfloat16* __restrict__ Agh,
                  const __nv_bfloat16* __restrict__ Agl, int lda,
                  const __nv_bfloat16* __restrict__ Bgh,
                  const __nv_bfloat16* __restrict__ Bgl,
                  const float* __restrict__ bias, float oscale,
                  float* __restrict__ C,
                  __nv_bfloat16* __restrict__ Ch,
                  __nv_bfloat16* __restrict__ Cl)
{
    constexpr int BM   = 128;
    constexpr int WM   = BM / 4;
    constexpr int WN   = BN / 2;
    constexpr int MT   = WM / 16;
    constexpr int NT   = WN / 8;
    constexpr int STR  = 40;
    constexpr int ASL  = BM * STR;
    constexpr int BSL  = BN * STR;
    constexpr int STG  = 2 * ASL + 2 * BSL;
    constexpr int NAC  = (BM * 4) / 256;
    constexpr int NBC  = (BN * 4) / 256;

    extern __shared__ __nv_bfloat16 smb[];

    const int tid  = threadIdx.x;
    const int lane = tid & 31;
    const int warp = tid >> 5;
    const int g    = lane >> 2;
    const int t    = lane & 3;
    const int wm   = warp >> 1;
    const int wn   = warp & 1;
    const int bRow = blockIdx.y * BM;
    const int bCol = blockIdx.x * BN;

    float acc[MT][NT][4];
#pragma unroll
    for (int mt = 0; mt < MT; mt++)
#pragma unroll
        for (int nt = 0; nt < NT; nt++)
#pragma unroll
            for (int i = 0; i < 4; i++) acc[mt][nt][i] = 0.f;

    auto issue = [&](int k0, int s) {
        __nv_bfloat16* st = smb + s * STG;
#pragma unroll
        for (int i = 0; i < NAC; i++) {
            int idx = tid + i * 256;
            int r = idx >> 2, c = idx & 3;
            uint32_t d = sptr(st + r * STR + c * 8);
            cp16(d, Agh + (size_t)(bRow + r) * lda + k0 + c * 8);
            cp16(d + ASL * 2, Agl + (size_t)(bRow + r) * lda + k0 + c * 8);
        }
#pragma unroll
        for (int i = 0; i < NBC; i++) {
            int idx = tid + i * 256;
            int r = idx >> 2, c = idx & 3;
            uint32_t d = sptr(st + 2 * ASL + r * STR + c * 8);
            cp16(d, Bgh + (size_t)(bCol + r) * K + k0 + c * 8);
            cp16(d + BSL * 2, Bgl + (size_t)(bCol + r) * K + k0 + c * 8);
        }
        cp_commit();
    };

    const int iters = K / 32;
    issue(0, 0);

    for (int it = 0; it < iters; it++) {
        const int cur = it & 1;
        if (it + 1 < iters) { issue((it + 1) * 32, cur ^ 1); cp_wait<1>(); }
        else                { cp_wait<0>(); }
        __syncthreads();

        const __nv_bfloat16* Ah = smb + cur * STG;
        const __nv_bfloat16* Al = Ah + ASL;
        const __nv_bfloat16* Bh = Ah + 2 * ASL;
        const __nv_bfloat16* Bl = Bh + BSL;

#pragma unroll
        for (int s = 0; s < 2; s++) {
            const int kb = 16 * s + 2 * t;
            uint32_t ah[MT][4], al[MT][4];
#pragma unroll
            for (int mt = 0; mt < MT; mt++) {
                int r0 = wm * WM + mt * 16 + g;
                int r1 = r0 + 8;
                ah[mt][0] = *reinterpret_cast<const uint32_t*>(&Ah[r0 * STR + kb]);
                ah[mt][1] = *reinterpret_cast<const uint32_t*>(&Ah[r1 * STR + kb]);
                ah[mt][2] = *reinterpret_cast<const uint32_t*>(&Ah[r0 * STR + kb + 8]);
                ah[mt][3] = *reinterpret_cast<const uint32_t*>(&Ah[r1 * STR + kb + 8]);
                al[mt][0] = *reinterpret_cast<const uint32_t*>(&Al[r0 * STR + kb]);
                al[mt][1] = *reinterpret_cast<const uint32_t*>(&Al[r1 * STR + kb]);
                al[mt][2] = *reinterpret_cast<const uint32_t*>(&Al[r0 * STR + kb + 8]);
                al[mt][3] = *reinterpret_cast<const uint32_t*>(&Al[r1 * STR + kb + 8]);
            }
#pragma unroll
            for (int nt = 0; nt < NT; nt++) {
                int nb = wn * WN + nt * 8 + g;
                uint32_t bh0 = *reinterpret_cast<const uint32_t*>(&Bh[nb * STR + kb]);
                uint32_t bh1 = *reinterpret_cast<const uint32_t*>(&Bh[nb * STR + kb + 8]);
                uint32_t bl0 = *reinterpret_cast<const uint32_t*>(&Bl[nb * STR + kb]);
                uint32_t bl1 = *reinterpret_cast<const uint32_t*>(&Bl[nb * STR + kb + 8]);
#pragma unroll
                for (int mt = 0; mt < MT; mt++) {
                    mma16(acc[mt][nt], ah[mt], bh0, bh1);
                    mma16(acc[mt][nt], ah[mt], bl0, bl1);
                    mma16(acc[mt][nt], al[mt], bh0, bh1);
                }
            }
        }
        __syncthreads();
    }

#pragma unroll
    for (int mt = 0; mt < MT; mt++) {
        int r0 = bRow + wm * WM + mt * 16 + g;
#pragma unroll
        for (int nt = 0; nt < NT; nt++) {
            int col = bCol + wn * WN + nt * 8 + 2 * t;
            float bx = bias[col], by = bias[col + 1];
            float v00 = (acc[mt][nt][0] + bx) * oscale, v01 = (acc[mt][nt][1] + by) * oscale;
            float v10 = (acc[mt][nt][2] + bx) * oscale, v11 = (acc[mt][nt][3] + by) * oscale;
            if (TF32O) {
                v00 = __uint_as_float(f2tf(v00)); v01 = __uint_as_float(f2tf(v01));
                v10 = __uint_as_float(f2tf(v10)); v11 = __uint_as_float(f2tf(v11));
            }
            if (!SPLIT_OUT) {
                float2 a = {v00, v01}, b = {v10, v11};
                *reinterpret_cast<float2*>(C + (size_t)r0 * N + col)       = a;
                *reinterpret_cast<float2*>(C + (size_t)(r0 + 8) * N + col) = b;
            } else {
                uint32_t h0, l0, h1, l1;
                split2(v00, v01, h0, l0);
                split2(v10, v11, h1, l1);
                *reinterpret_cast<uint32_t*>(&Ch[(size_t)r0 * N + col])       = h0;
                *reinterpret_cast<uint32_t*>(&Cl[(size_t)r0 * N + col])       = l0;
                *reinterpret_cast<uint32_t*>(&Ch[(size_t)(r0 + 8) * N + col]) = h1;
                *reinterpret_cast<uint32_t*>(&Cl[(size_t)(r0 + 8) * N + col]) = l1;
            }
        }
    }
}

// ---------------------------------------------------------------------------
// RoPE in-place; output rounded to tf32 grid (consumed raw by attention).
// ---------------------------------------------------------------------------
__global__ void rope_kernel(float* __restrict__ x, int D)
{
    const int pairs = D / 2;
    int idx = blockIdx.x * blockDim.x + threadIdx.x;
    if (idx >= MR * pairs) return;
    int row = idx / pairs;
    int i   = idx - row * pairs;
    int t   = row & (TT - 1);

    float theta = expf(-2.0f * (float)i / (float)D * 9.2103403719761836f);
    float ang   = (float)(t + 1) * theta;
    float sn, cs;
    sincosf(ang, &sn, &cs);

    float* p = x + (size_t)row * D + 2*i;
    float e = p[0], o = p[1];
    p[0] = __uint_as_float(f2tf(e * cs - o * sn));
    p[1] = __uint_as_float(f2tf(o * cs + e * sn));
}

// ---------------------------------------------------------------------------
// Causal flash attention, tf32 mma.sync, cp.async double-buffered K/V.
// Q/K/V arrive tf32-rounded + pre-scaled from producers -> zero cvt in loop.
// Q smem [r][d] stride 132; K smem [key][d] stride 132 (conflict-free frags).
// ---------------------------------------------------------------------------
#define QST 132
#define KST 132
#define VST 72
#define PST 68

#define OFF_K (128 * QST)
#define OFF_V (OFF_K + 2 * 64 * KST)
#define OFF_P (OFF_V + 2 * 64 * VST)
#define ATT_WORDS (OFF_P + 128 * PST)   // 51712 words = 206848 B

__global__ __launch_bounds__(256, 1)
void attn_tc_kernel()
{
    extern __shared__ float sm[];
    float* Qs = sm;
    float* Ps = sm + OFF_P;

    const int tid  = threadIdx.x;
    const int lane = tid & 31;
    const int warp = tid >> 5;
    const int g    = lane >> 2;
    const int t    = lane & 3;
    const int qt   = (gridDim.x - 1) - blockIdx.x;   // heavy blocks first
    const int hh   = blockIdx.y;
    const int b    = blockIdx.z;
    const int rowBase = b * TT + qt * 128;

    auto issueKV = [&](int j, int s) {
        float* Kt = sm + OFF_K + s * 64 * KST;
        float* Vt = sm + OFF_V + s * 64 * VST;
        const int kbase = b * TT + j * 64;
#pragma unroll
        for (int i = 0; i < 8; i++) {
            int idx = tid + i * 256;
            int r = idx >> 5, c = idx & 31;
            uint32_t d = sptr(Kt + r * KST + c * 4);
            if (c < 16) cp16(d, g_kv + (size_t)(kbase + r) * 2048 + hh * 64 + c * 4);
            else        cp16(d, g_kr + (size_t)(kbase + r) * 64 + (c - 16) * 4);
        }
#pragma unroll
        for (int i = 0; i < 4; i++) {
            int idx = tid + i * 256;
            int r = idx >> 4, c = idx & 15;
            cp16(sptr(Vt + r * VST + c * 4),
                 g_kv + (size_t)(kbase + r) * 2048 + 1024 + hh * 64 + c * 4);
        }
        cp_commit();
    };

    // Q tile + first K/V tile (group 0)
#pragma unroll
    for (int i = 0; i < 16; i++) {
        int idx = tid + i * 256;
        int r = idx >> 5, c = idx & 31;
        uint32_t d = sptr(Qs + r * QST + c * 4);
        if (c < 16) cp16(d, g_q  + (size_t)(rowBase + r) * 1024 + hh * 64 + c * 4);
        else        cp16(d, g_qr + (size_t)(rowBase + r) * 1024 + hh * 64 + (c - 16) * 4);
    }
    issueKV(0, 0);

    const int rloc0 = warp * 16 + g;
    float m0 = -1e30f, m1 = -1e30f, l0 = 0.f, l1 = 0.f;
    float o[8][4];
#pragma unroll
    for (int nt = 0; nt < 8; nt++)
#pragma unroll
        for (int i = 0; i < 4; i++) o[nt][i] = 0.f;

    const int nkt = 2 * qt + 2;
    for (int j = 0; j < nkt; j++) {
        const int s = j & 1;
        if (j + 1 < nkt) { issueKV(j + 1, s ^ 1); cp_wait<1>(); }
        else             { cp_wait<0>(); }
        __syncthreads();                     // tile j visible; buf s^1 safe (compute j-1 done)

        const float* Kt = sm + OFF_K + s * 64 * KST;
        const float* Vt = sm + OFF_V + s * 64 * VST;

        // --- S = Q @ K^T -----------------------------------------------------
        float sc[8][4];
#pragma unroll
        for (int nt = 0; nt < 8; nt++)
#pragma unroll
            for (int i = 0; i < 4; i++) sc[nt][i] = 0.f;

#pragma unroll
        for (int ks = 0; ks < 16; ks++) {
            uint32_t a0 = __float_as_uint(Qs[(rloc0)     * QST + ks * 8 + t]);
            uint32_t a1 = __float_as_uint(Qs[(rloc0 + 8) * QST + ks * 8 + t]);
            uint32_t a2 = __float_as_uint(Qs[(rloc0)     * QST + ks * 8 + t + 4]);
            uint32_t a3 = __float_as_uint(Qs[(rloc0 + 8) * QST + ks * 8 + t + 4]);
#pragma unroll
            for (int nt = 0; nt < 8; nt++) {
                uint32_t b0 = __float_as_uint(Kt[(nt * 8 + g) * KST + ks * 8 + t]);
                uint32_t b1 = __float_as_uint(Kt[(nt * 8 + g) * KST + ks * 8 + t + 4]);
                mma8(sc[nt], a0, a1, a2, a3, b0, b1);
            }
        }

        // --- causal mask -----------------------------------------------------
        if (j >= 2 * qt) {
            int rg0 = qt * 128 + rloc0;
            int k0 = j * 64;
#pragma unroll
            for (int nt = 0; nt < 8; nt++) {
                int cg = k0 + nt * 8 + 2 * t;
                if (cg     > rg0)     sc[nt][0] = -1e30f;
                if (cg + 1 > rg0)     sc[nt][1] = -1e30f;
                if (cg     > rg0 + 8) sc[nt][2] = -1e30f;
                if (cg + 1 > rg0 + 8) sc[nt][3] = -1e30f;
            }
        }

        // --- online softmax (registers + 4-lane shfl) ------------------------
        float mx0 = -1e30f, mx1 = -1e30f;
#pragma unroll
        for (int nt = 0; nt < 8; nt++) {
            mx0 = fmaxf(mx0, fmaxf(sc[nt][0], sc[nt][1]));
            mx1 = fmaxf(mx1, fmaxf(sc[nt][2], sc[nt][3]));
        }
        mx0 = fmaxf(mx0, __shfl_xor_sync(0xffffffffu, mx0, 1));
        mx0 = fmaxf(mx0, __shfl_xor_sync(0xffffffffu, mx0, 2));
        mx1 = fmaxf(mx1, __shfl_xor_sync(0xffffffffu, mx1, 1));
        mx1 = fmaxf(mx1, __shfl_xor_sync(0xffffffffu, mx1, 2));

        float mn0 = fmaxf(m0, mx0), mn1 = fmaxf(m1, mx1);
        float al0 = __expf(m0 - mn0), al1 = __expf(m1 - mn1);
        m0 = mn0; m1 = mn1;

        float sum0 = 0.f, sum1 = 0.f;
#pragma unroll
        for (int nt = 0; nt < 8; nt++) {
            float p0 = __expf(sc[nt][0] - mn0);
            float p1 = __expf(sc[nt][1] - mn0);
            float p2 = __expf(sc[nt][2] - mn1);
            float p3 = __expf(sc[nt][3] - mn1);
            sum0 += p0 + p1; sum1 += p2 + p3;
            float2 w0 = {__uint_as_float(f2tf(p0)), __uint_as_float(f2tf(p1))};
            float2 w1 = {__uint_as_float(f2tf(p2)), __uint_as_float(f2tf(p3))};
            *reinterpret_cast<float2*>(&Ps[(rloc0)     * PST + nt * 8 + 2 * t]) = w0;
            *reinterpret_cast<float2*>(&Ps[(rloc0 + 8) * PST + nt * 8 + 2 * t]) = w1;
        }
        sum0 += __shfl_xor_sync(0xffffffffu, sum0, 1);
        sum0 += __shfl_xor_sync(0xffffffffu, sum0, 2);
        sum1 += __shfl_xor_sync(0xffffffffu, sum1, 1);
        sum1 += __shfl_xor_sync(0xffffffffu, sum1, 2);
        l0 = l0 * al0 + sum0;
        l1 = l1 * al1 + sum1;

#pragma unroll
        for (int nt = 0; nt < 8; nt++) {
            o[nt][0] *= al0; o[nt][1] *= al0;
            o[nt][2] *= al1; o[nt][3] *= al1;
        }
        __syncwarp();   // Ps exchange is intra-warp only

        // --- O += P @ V ------------------------------------------------------
#pragma unroll
        for (int ks = 0; ks < 8; ks++) {
            uint32_t a0 = __float_as_uint(Ps[(rloc0)     * PST + ks * 8 + t]);
            uint32_t a1 = __float_as_uint(Ps[(rloc0 + 8) * PST + ks * 8 + t]);
            uint32_t a2 = __float_as_uint(Ps[(rloc0)     * PST + ks * 8 + t + 4]);
            uint32_t a3 = __float_as_uint(Ps[(rloc0 + 8) * PST + ks * 8 + t + 4]);
#pragma unroll
            for (int nt = 0; nt < 8; nt++) {
                uint32_t b0 = __float_as_uint(Vt[(ks * 8 + t)     * VST + nt * 8 + g]);
                uint32_t b1 = __float_as_uint(Vt[(ks * 8 + t + 4) * VST + nt * 8 + g]);
                mma8(o[nt], a0, a1, a2, a3, b0, b1);
            }
        }
        __syncthreads();   // done with buf s before next iter issues into it
    }

    // finalize + store split bf16 (att feeds only the wo GEMM)
    float inv0 = 1.0f / l0, inv1 = 1.0f / l1;
    int rg = rowBase + rloc0;
#pragma unroll
    for (int nt = 0; nt < 8; nt++) {
        int col = hh * 64 + nt * 8 + 2 * t;
        uint32_t h0, l0u, h1, l1u;
        split2(o[nt][0] * inv0, o[nt][1] * inv0, h0, l0u);
        split2(o[nt][2] * inv1, o[nt][3] * inv1, h1, l1u);
        *reinterpret_cast<uint32_t*>(&g_ath[(size_t)rg       * 1024 + col]) = h0;
        *reinterpret_cast<uint32_t*>(&g_atl[(size_t)rg       * 1024 + col]) = l0u;
        *reinterpret_cast<uint32_t*>(&g_ath[(size_t)(rg + 8) * 1024 + col]) = h1;
        *reinterpret_cast<uint32_t*>(&g_atl[(size_t)(rg + 8) * 1024 + col]) = l1u;
    }
}

// ---------------------------------------------------------------------------
// Launch
// ---------------------------------------------------------------------------
extern "C" void kernel_launch(void* const* d_in, const int* in_sizes, int n_in,
                              void* d_out, int out_size)
{
    (void)in_sizes; (void)n_in; (void)out_size;
    const float* x   = (const float*)d_in[0];
    const float* w1  = (const float*)d_in[1];
    const float* b1  = (const float*)d_in[2];
    const float* wkr = (const float*)d_in[3];
    const float* bkr = (const float*)d_in[4];
    const float* wqr = (const float*)d_in[5];
    const float* bqr = (const float*)d_in[6];
    const float* wkv = (const float*)d_in[7];
    const float* bkv = (const float*)d_in[8];
    const float* wq  = (const float*)d_in[9];
    const float* bq  = (const float*)d_in[10];
    const float* wo  = (const float*)d_in[11];
    const float* bo  = (const float*)d_in[12];
    float* out = (float*)d_out;
    const float scale = 0.08838834764831845f;   // 128^-0.5

    float *kr_, *qr_, *kv_, *q_;
    __nv_bfloat16 *xh_, *xl_, *hh_, *hl_, *ath_, *atl_;
    __nv_bfloat16 *w1h_, *w1l_, *wkrh_, *wkrl_, *wqrh_, *wqrl_;
    __nv_bfloat16 *wkvh_, *wkvl_, *wqh_, *wql_, *woh_, *wol_;
    cudaGetSymbolAddress((void**)&kr_,  g_kr);
    cudaGetSymbolAddress((void**)&qr_,  g_qr);
    cudaGetSymbolAddress((void**)&kv_,  g_kv);
    cudaGetSymbolAddress((void**)&q_,   g_q);
    cudaGetSymbolAddress((void**)&xh_,  g_xh);  cudaGetSymbolAddress((void**)&xl_,  g_xl);
    cudaGetSymbolAddress((void**)&hh_,  g_hh);  cudaGetSymbolAddress((void**)&hl_,  g_hl);
    cudaGetSymbolAddress((void**)&ath_, g_ath); cudaGetSymbolAddress((void**)&atl_, g_atl);
    cudaGetSymbolAddress((void**)&w1h_, g_w1h);  cudaGetSymbolAddress((void**)&w1l_, g_w1l);
    cudaGetSymbolAddress((void**)&wkrh_, g_wkrh); cudaGetSymbolAddress((void**)&wkrl_, g_wkrl);
    cudaGetSymbolAddress((void**)&wqrh_, g_wqrh); cudaGetSymbolAddress((void**)&wqrl_, g_wqrl);
    cudaGetSymbolAddress((void**)&wkvh_, g_wkvh); cudaGetSymbolAddress((void**)&wkvl_, g_wkvl);
    cudaGetSymbolAddress((void**)&wqh_, g_wqh);   cudaGetSymbolAddress((void**)&wql_, g_wql);
    cudaGetSymbolAddress((void**)&woh_, g_woh);   cudaGetSymbolAddress((void**)&wol_, g_wol);

    const int SMG128 = 2 * (2 * 128 * 40 + 2 * 128 * 40) * 2;   // 81920
    const int SMG64  = 2 * (2 * 128 * 40 + 2 * 64  * 40) * 2;   // 61440
    const int SMAT   = ATT_WORDS * 4;                            // 206848
    cudaFuncSetAttribute(gemm_bf16_3x<128, true,  false>, cudaFuncAttributeMaxDynamicSharedMemorySize, SMG128);
    cudaFuncSetAttribute(gemm_bf16_3x<128, false, true>,  cudaFuncAttributeMaxDynamicSharedMemorySize, SMG128);
    cudaFuncSetAttribute(gemm_bf16_3x<128, false, false>, cudaFuncAttributeMaxDynamicSharedMemorySize, SMG128);
    cudaFuncSetAttribute(gemm_bf16_3x<64,  false, false>, cudaFuncAttributeMaxDynamicSharedMemorySize, SMG64);
    cudaFuncSetAttribute(attn_tc_kernel, cudaFuncAttributeMaxDynamicSharedMemorySize, SMAT);

    dim3 wsb(32, 8);
    wsplit_kernel<<<dim3(1024/32, 1024/32), wsb>>>(w1,  1024, 1024, w1h_,  w1l_);
    wsplit_kernel<<<dim3(64/32,   1024/32), wsb>>>(wkr, 1024, 64,   wkrh_, wkrl_);
    wsplit_kernel<<<dim3(1024/32, 1024/32), wsb>>>(wqr, 1024, 1024, wqrh_, wqrl_);
    wsplit_kernel<<<dim3(2048/32, 512/32),  wsb>>>(wkv, 512,  2048, wkvh_, wkvl_);
    wsplit_kernel<<<dim3(1024/32, 512/32),  wsb>>>(wq,  512,  1024, wqh_,  wql_);
    wsplit_kernel<<<dim3(1024/32, 1024/32), wsb>>>(wo,  1024, 1024, woh_,  wol_);
    asplit_kernel<<<(MR * 1024 / 4 + 255) / 256, 256>>>(
        (const float4*)x, (uint2*)xh_, (uint2*)xl_, MR * 1024 / 4);

    // 1) h = x @ w1 + b1  -> split bf16 h
    gemm_bf16_3x<128, true, false><<<dim3(8, 32), 256, SMG128>>>(
        1024, 1024, xh_, xl_, 1024, w1h_, w1l_, b1, 1.f, nullptr, hh_, hl_);

    // 2) kr = rope(h @ wkr + bkr)   (rope rounds to tf32)
    gemm_bf16_3x<64, false, false><<<dim3(1, 32), 256, SMG64>>>(
        64, 1024, hh_, hl_, 1024, wkrh_, wkrl_, bkr, 1.f, kr_, nullptr, nullptr);
    rope_kernel<<<(MR * 32 + 255) / 256, 256>>>(kr_, 64);

    // 3) qr = rope((h @ wqr + bqr) * scale)  (scale folded; rope rounds to tf32)
    gemm_bf16_3x<128, false, false><<<dim3(8, 32), 256, SMG128>>>(
        1024, 1024, hh_, hl_, 1024, wqrh_, wqrl_, bqr, scale, qr_, nullptr, nullptr);
    rope_kernel<<<(MR * 512 + 255) / 256, 256>>>(qr_, 1024);

    // 4) kv = cKV @ wkv + bkv  -> tf32-rounded
    gemm_bf16_3x<128, false, true><<<dim3(16, 32), 256, SMG128>>>(
        2048, 512, hh_, hl_, 1024, wkvh_, wkvl_, bkv, 1.f, kv_, nullptr, nullptr);

    // 5) q = (cq @ wq + bq) * scale  -> tf32-rounded
    gemm_bf16_3x<128, false, true><<<dim3(8, 32), 256, SMG128>>>(
        1024, 512, hh_ + 512, hl_ + 512, 1024, wqh_, wql_, bq, scale, q_, nullptr, nullptr);

    // 6) attention -> split bf16 att
    attn_tc_kernel<<<dim3(16, NH, BB), 256, SMAT>>>();

    // 7) out = att @ wo + bo
    gemm_bf16_3x<128, false, false><<<dim3(8, 32), 256, SMG128>>>(
        1024, 1024, ath_, atl_, 1024, woh_, wol_, bo, 1.f, out, nullptr, nullptr);
}